// round 14
// baseline (speedup 1.0000x reference)
#include <cuda_runtime.h>
#include <cuda_fp16.h>

// Problem constants (fixed shapes from reference)
#define BB 4
#define SS 4096
#define DD 1024
#define HD 128
#define BS (BB*SS)   // 16384 rows
#define RR 16        // scan lookahead block size
#define NBLK (SS/RR) // 256
#define CC 64        // chunk size for y reconstruction
#define NCH (SS/CC)

// ---------------------------------------------------------------------------
// Scratch (device globals; no allocation allowed in kernel_launch)
// ---------------------------------------------------------------------------
__device__ float g_q[BB*SS*HD];
__device__ float g_k[BB*SS*HD];
__device__ float g_v[BB*SS*HD];
__device__ float g_y[BB*SS*HD];
__device__ float g_e[BB*SS*HD];
__device__ float g_gram16[BB*SS*16];      // per (b,t): G1..G15, pad; Gd = k_{t-d}.k_t
__device__ float g_wsnap[BB*NCH*HD*HD];   // W at chunk starts

// fp16-split operands: q-path ONLY (k/v feed the recurrence -> coherent split
// error is amplified ~linearly in S; q has no feedback and is safe)
__device__ __half g_xh[BS*DD], g_xl[BS*DD];
__device__ __half g_wqh[HD*DD], g_wql[HD*DD];   // Wq^T [HD][DD]

__device__ __forceinline__ float dot4(float4 a, float4 b) {
    return fmaf(a.x, b.x, fmaf(a.y, b.y, fmaf(a.z, b.z, a.w * b.w)));
}

// ---------------------------------------------------------------------------
// Split kernels: a = hi(fp16) + lo(fp16)
// ---------------------------------------------------------------------------
__global__ __launch_bounds__(256) void splitx_kernel(const float* __restrict__ x)
{
    const size_t i = (size_t)blockIdx.x * blockDim.x + threadIdx.x;  // float4 idx
    const float4 f = ((const float4*)x)[i];
    __half h0 = __float2half_rn(f.x), h1 = __float2half_rn(f.y);
    __half h2 = __float2half_rn(f.z), h3 = __float2half_rn(f.w);
    __half l0 = __float2half_rn(f.x - __half2float(h0));
    __half l1 = __float2half_rn(f.y - __half2float(h1));
    __half l2 = __float2half_rn(f.z - __half2float(h2));
    __half l3 = __float2half_rn(f.w - __half2float(h3));
    ((__half2*)g_xh)[2*i]     = __halves2half2(h0, h1);
    ((__half2*)g_xh)[2*i + 1] = __halves2half2(h2, h3);
    ((__half2*)g_xl)[2*i]     = __halves2half2(l0, l1);
    ((__half2*)g_xl)[2*i + 1] = __halves2half2(l2, l3);
}

__global__ __launch_bounds__(256) void splitwq_kernel(const float* __restrict__ Wq)
{
    const int r = blockIdx.x * blockDim.x + threadIdx.x;   // 0 .. DD*HD-1
    const int d = r >> 7, h = r & 127;
    const float f = Wq[r];
    __half hi = __float2half_rn(f);
    __half lo = __float2half_rn(f - __half2float(hi));
    g_wqh[h * DD + d] = hi;
    g_wql[h * DD + d] = lo;
}

// ---------------------------------------------------------------------------
// fp16-split tensor-core GEMM (3-term): q = x * Wq^T
// CTA tile 128x128, K-step 32, 8 warps (2x4), warp tile 64x32, m16n8k16.
// ---------------------------------------------------------------------------
__device__ __forceinline__ void mma16816(float* c, const unsigned* a, const unsigned* b)
{
    asm volatile(
        "mma.sync.aligned.m16n8k16.row.col.f32.f16.f16.f32 "
        "{%0,%1,%2,%3},{%4,%5,%6,%7},{%8,%9},{%0,%1,%2,%3};"
        : "+f"(c[0]), "+f"(c[1]), "+f"(c[2]), "+f"(c[3])
        : "r"(a[0]), "r"(a[1]), "r"(a[2]), "r"(a[3]), "r"(b[0]), "r"(b[1]));
}

__global__ __launch_bounds__(256) void qmma_kernel()
{
    __shared__ unsigned AsH[128*20], AsL[128*20], BsH[128*20], BsL[128*20];

    const int bm = blockIdx.x;
    const int N = HD, K = DD;

    const int t = threadIdx.x;
    const int lane = t & 31, wid = t >> 5;
    const int g = lane >> 2, tg = lane & 3;
    const int warpM = wid >> 2, warpN = wid & 3;

    const int lr = t >> 1, lc = t & 1;
    const __half* aPh = g_xh + (size_t)(bm * 128 + lr) * K + lc * 16;
    const __half* aPl = g_xl + (size_t)(bm * 128 + lr) * K + lc * 16;
    const __half* bPh = g_wqh + (size_t)lr * K + lc * 16;
    const __half* bPl = g_wql + (size_t)lr * K + lc * 16;
    const int sts = lr * 20 + lc * 8;

    float c[4][4][4];
#pragma unroll
    for (int mt = 0; mt < 4; mt++)
#pragma unroll
        for (int nt = 0; nt < 4; nt++)
#pragma unroll
            for (int j = 0; j < 4; j++) c[mt][nt][j] = 0.f;

    int4 ra0  = *(const int4*)aPh;       int4 ra1  = *(const int4*)(aPh + 8);
    int4 ral0 = *(const int4*)aPl;       int4 ral1 = *(const int4*)(aPl + 8);
    int4 rb0  = *(const int4*)bPh;       int4 rb1  = *(const int4*)(bPh + 8);
    int4 rbl0 = *(const int4*)bPl;       int4 rbl1 = *(const int4*)(bPl + 8);
    *(int4*)&AsH[sts] = ra0;   *(int4*)&AsH[sts + 4] = ra1;
    *(int4*)&AsL[sts] = ral0;  *(int4*)&AsL[sts + 4] = ral1;
    *(int4*)&BsH[sts] = rb0;   *(int4*)&BsH[sts + 4] = rb1;
    *(int4*)&BsL[sts] = rbl0;  *(int4*)&BsL[sts + 4] = rbl1;
    __syncthreads();

    const int KT = K / 32;
    for (int kt = 0; kt < KT; kt++) {
        if (kt + 1 < KT) {
            const int o = (kt + 1) * 32;
            ra0  = *(const int4*)(aPh + o);      ra1  = *(const int4*)(aPh + o + 8);
            ral0 = *(const int4*)(aPl + o);      ral1 = *(const int4*)(aPl + o + 8);
            rb0  = *(const int4*)(bPh + o);      rb1  = *(const int4*)(bPh + o + 8);
            rbl0 = *(const int4*)(bPl + o);      rbl1 = *(const int4*)(bPl + o + 8);
        }
#pragma unroll
        for (int s = 0; s < 2; s++) {
            unsigned aH[4][4], aL[4][4], bH[4][2], bL[4][2];
#pragma unroll
            for (int mt = 0; mt < 4; mt++) {
                const int r0 = (warpM * 64 + mt * 16 + g) * 20 + s * 8 + tg;
                aH[mt][0] = AsH[r0];       aH[mt][1] = AsH[r0 + 160];
                aH[mt][2] = AsH[r0 + 4];   aH[mt][3] = AsH[r0 + 164];
                aL[mt][0] = AsL[r0];       aL[mt][1] = AsL[r0 + 160];
                aL[mt][2] = AsL[r0 + 4];   aL[mt][3] = AsL[r0 + 164];
            }
#pragma unroll
            for (int nt = 0; nt < 4; nt++) {
                const int n0 = (warpN * 32 + nt * 8 + g) * 20 + s * 8 + tg;
                bH[nt][0] = BsH[n0];  bH[nt][1] = BsH[n0 + 4];
                bL[nt][0] = BsL[n0];  bL[nt][1] = BsL[n0 + 4];
            }
#pragma unroll
            for (int mt = 0; mt < 4; mt++)
#pragma unroll
                for (int nt = 0; nt < 4; nt++) {
                    mma16816(c[mt][nt], aH[mt], bH[nt]);
                    mma16816(c[mt][nt], aH[mt], bL[nt]);
                    mma16816(c[mt][nt], aL[mt], bH[nt]);
                }
        }
        __syncthreads();
        if (kt + 1 < KT) {
            *(int4*)&AsH[sts] = ra0;   *(int4*)&AsH[sts + 4] = ra1;
            *(int4*)&AsL[sts] = ral0;  *(int4*)&AsL[sts + 4] = ral1;
            *(int4*)&BsH[sts] = rb0;   *(int4*)&BsH[sts + 4] = rb1;
            *(int4*)&BsL[sts] = rbl0;  *(int4*)&BsL[sts + 4] = rbl1;
            __syncthreads();
        }
    }

#pragma unroll
    for (int mt = 0; mt < 4; mt++)
#pragma unroll
        for (int nt = 0; nt < 4; nt++) {
            const int row = bm * 128 + warpM * 64 + mt * 16 + g;
            const int col = warpN * 32 + nt * 8 + 2 * tg;
            *(float2*)&g_q[(size_t)row * N + col]       = make_float2(c[mt][nt][0], c[mt][nt][1]);
            *(float2*)&g_q[(size_t)(row + 8) * N + col] = make_float2(c[mt][nt][2], c[mt][nt][3]);
        }
}

// ---------------------------------------------------------------------------
// fp32 SGEMM body (known good): C = A[M,K]*B[K,N]
// ---------------------------------------------------------------------------
__device__ __forceinline__ void sgemm_body(
    const float* __restrict__ A, const float* __restrict__ Bm,
    float* __restrict__ C, int M, int N, int K, int bx, int by)
{
    __shared__ float As[8][128];
    __shared__ float Bs[8][132];

    const int tid = threadIdx.x;
    const int ty = tid >> 4;
    const int tx = tid & 15;
    const int a_r = tid >> 1;
    const int a_c = (tid & 1) << 2;
    const int b_r = tid >> 5;
    const int b_c = (tid & 31) << 2;

    const float* Ab = A + (size_t)by * 128 * K;
    const float* Bb = Bm + bx * 128;

    float acc[8][8];
#pragma unroll
    for (int i = 0; i < 8; i++)
#pragma unroll
        for (int j = 0; j < 8; j++) acc[i][j] = 0.f;

    for (int k0 = 0; k0 < K; k0 += 8) {
        float4 av = *(const float4*)(Ab + (size_t)a_r * K + k0 + a_c);
        float4 bv = *(const float4*)(Bb + (size_t)(k0 + b_r) * N + b_c);
        __syncthreads();
        As[a_c + 0][a_r] = av.x;
        As[a_c + 1][a_r] = av.y;
        As[a_c + 2][a_r] = av.z;
        As[a_c + 3][a_r] = av.w;
        *(float4*)&Bs[b_r][b_c] = bv;
        __syncthreads();
#pragma unroll
        for (int kk = 0; kk < 8; kk++) {
            float a[8], b[8];
#pragma unroll
            for (int i = 0; i < 8; i++) a[i] = As[kk][ty * 8 + i];
#pragma unroll
            for (int j = 0; j < 8; j++) b[j] = Bs[kk][tx * 8 + j];
#pragma unroll
            for (int i = 0; i < 8; i++)
#pragma unroll
                for (int j = 0; j < 8; j++) acc[i][j] = fmaf(a[i], b[j], acc[i][j]);
        }
    }

    float* Cb = C + (size_t)(by * 128 + ty * 8) * N + bx * 128 + tx * 8;
#pragma unroll
    for (int i = 0; i < 8; i++) {
        *(float4*)(Cb + (size_t)i * N)     = make_float4(acc[i][0], acc[i][1], acc[i][2], acc[i][3]);
        *(float4*)(Cb + (size_t)i * N + 4) = make_float4(acc[i][4], acc[i][5], acc[i][6], acc[i][7]);
    }
}

// Fused K,V projections in fp32 (recurrence-sensitive operands)
__global__ __launch_bounds__(256) void kvgemm_kernel(
    const float* __restrict__ x, const float* __restrict__ Wk,
    const float* __restrict__ Wv)
{
    const float* Bm = (blockIdx.z == 0) ? Wk : Wv;
    float* C = (blockIdx.z == 0) ? g_k : g_v;
    sgemm_body(x, Bm, C, BS, HD, DD, 0, blockIdx.y);
}

__global__ __launch_bounds__(256) void outgemm_kernel(
    const float* __restrict__ Wo, float* __restrict__ out)
{
    sgemm_body(g_y, Wo, out, BS, DD, HD, blockIdx.x, blockIdx.y);
}

// ---------------------------------------------------------------------------
// Gram kernel: one warp per (b,t): G_d[t] = k_{t-d}.k_t for d=1..15
// ---------------------------------------------------------------------------
__global__ __launch_bounds__(256) void gram_kernel()
{
    const int w = (blockIdx.x * blockDim.x + threadIdx.x) >> 5;  // b*SS + t
    const int lane = threadIdx.x & 31;
    if (w >= BB * SS) return;
    const int t = w & (SS - 1);

    float4 kc = *(const float4*)(g_k + (size_t)w * HD + lane * 4);
    float dd[15];
#pragma unroll
    for (int d2 = 1; d2 <= 15; d2++) {
        float4 kd = make_float4(0.f, 0.f, 0.f, 0.f);
        if (t >= d2) kd = *(const float4*)(g_k + (size_t)(w - d2) * HD + lane * 4);
        dd[d2 - 1] = dot4(kd, kc);
    }
#pragma unroll
    for (int s = 16; s; s >>= 1) {
#pragma unroll
        for (int j = 0; j < 15; j++) dd[j] += __shfl_xor_sync(~0u, dd[j], s);
    }
    if (lane == 0) {
        float* gp = g_gram16 + (size_t)w * 16;
        *(float4*)(gp)      = make_float4(dd[0],  dd[1],  dd[2],  dd[3]);
        *(float4*)(gp + 4)  = make_float4(dd[4],  dd[5],  dd[6],  dd[7]);
        *(float4*)(gp + 8)  = make_float4(dd[8],  dd[9],  dd[10], dd[11]);
        *(float4*)(gp + 12) = make_float4(dd[12], dd[13], dd[14], 0.f);
    }
}

// ---------------------------------------------------------------------------
// Blocked-lookahead error scan, R=16. k via 2-stage cp.async smem pipeline
// (depth-1 prefetch, wait_group 1); v depth-2 register prefetch; Gram via
// smem double buffer. One warp per (batch, W-row), 2 warps/CTA.
// ---------------------------------------------------------------------------
__device__ __forceinline__ void cp_async16(unsigned smem_addr, const void* gptr)
{
    asm volatile("cp.async.cg.shared.global [%0], [%1], 16;"
                 :: "r"(smem_addr), "l"(gptr));
}
__device__ __forceinline__ void cp_commit() {
    asm volatile("cp.async.commit_group;");
}
__device__ __forceinline__ void cp_wait1() {
    asm volatile("cp.async.wait_group 1;");
}

__global__ __launch_bounds__(64) void scan_kernel(
    const float* __restrict__ lr, const float* __restrict__ state,
    float* __restrict__ wfinal)
{
    __shared__ float  ksm[2][2][RR][HD];   // [warp][stage][row][float] = 32KB
    __shared__ float4 gwbuf[2][2][64];     // [warp][buffer][16t x 4f4] = 4KB

    const int warp = (blockIdx.x * blockDim.x + threadIdx.x) >> 5;  // 0..511
    const int wl = (threadIdx.x >> 5);
    const int lane = threadIdx.x & 31;
    const int b = warp >> 7;
    const int i = warp & 127;
    const float eta = __ldg(lr);

    const float* kp = g_k + (size_t)b * SS * HD;
    const float* vp = g_v + (size_t)b * SS * HD + i;
    const float4* gp4 = (const float4*)(g_gram16 + (size_t)b * SS * 16);
    float* ep = g_e + (size_t)b * SS * HD + i;

    float4 Wr = *(const float4*)(state + (size_t)(b * HD + i) * HD + lane * 4);

    unsigned kbase = (unsigned)__cvta_generic_to_shared(&ksm[wl][0][0][lane * 4]);
    const unsigned KSTAGE = RR * HD * 4;   // 8192 bytes

    float vc[RR], vn1[RR], vn2[RR];
    // prologue: stage0 <- block0
#pragma unroll
    for (int r = 0; r < RR; r++)
        cp_async16(kbase + r * (HD * 4), kp + (size_t)r * HD + lane * 4);
    cp_commit();
#pragma unroll
    for (int r = 0; r < RR; r++) {
        vc[r]  = vp[(size_t)r * HD];
        vn1[r] = vp[(size_t)(RR + r) * HD];
    }
    gwbuf[wl][0][lane]      = gp4[lane];
    gwbuf[wl][0][lane + 32] = gp4[lane + 32];
    __syncwarp();

    for (int blk = 0; blk < NBLK; blk++) {
        const int T = blk * RR;
        const int cur = blk & 1;

        // chunk-start snapshot (Wr == W_{T-1}; CC/RR = 4)
        if ((blk & 3) == 0) {
            const int c = blk >> 2;
            *(float4*)(g_wsnap + ((size_t)((b * NCH + c) * HD + i)) * HD + lane * 4) = Wr;
        }

        // prefetch k for blk+1 into stage cur^1
        const int T1 = ((blk + 1 < NBLK) ? (blk + 1) : (NBLK - 1)) * RR;
#pragma unroll
        for (int r = 0; r < RR; r++)
            cp_async16(kbase + (cur ^ 1) * KSTAGE + r * (HD * 4),
                       kp + (size_t)(T1 + r) * HD + lane * 4);
        cp_commit();

        // v prefetch depth 2 (registers)
        const int T2 = ((blk + 2 < NBLK) ? (blk + 2) : (NBLK - 1)) * RR;
#pragma unroll
        for (int r = 0; r < RR; r++) vn2[r] = vp[(size_t)(T2 + r) * HD];

        // gram prefetch depth 1 (registers)
        float4 ga = gp4[(size_t)T1 * 4 + lane];
        float4 gb = gp4[(size_t)T1 * 4 + 32 + lane];

        // current k stage ready once only the just-issued group is outstanding
        cp_wait1();

        // 16 dots against fixed basis (each lane reads the 16B it copied)
        float d[RR];
#pragma unroll
        for (int r = 0; r < RR; r++) {
            float4 kk4 = *(const float4*)&ksm[wl][cur][r][lane * 4];
            d[r] = dot4(kk4, Wr);
        }
        // pipelined 5-stage shuffle reduction over 16 independent values
#pragma unroll
        for (int s = 16; s; s >>= 1) {
#pragma unroll
            for (int j = 0; j < RR; j++) d[j] += __shfl_xor_sync(~0u, d[j], s);
        }

        // publish next gram block
        gwbuf[wl][cur ^ 1][lane]      = ga;
        gwbuf[wl][cur ^ 1][lane + 32] = gb;
        __syncwarp();

        // serial scalar recurrence; Gram scalars read straight from smem
        const float* gbuf = (const float*)&gwbuf[wl][cur][0];
        float e[RR], ee[RR];
#pragma unroll
        for (int r = 0; r < RR; r++) {
            float acc = d[r] - vc[r];
#pragma unroll
            for (int dd2 = r; dd2 >= 1; --dd2)
                acc = fmaf(-ee[r - dd2], gbuf[r * 16 + dd2 - 1], acc);
            e[r] = acc;
            ee[r] = eta * acc;
        }

        if (lane == 0) {
#pragma unroll
            for (int r = 0; r < RR; r++) ep[(size_t)(T + r) * HD] = e[r];
        }

        // rank-16 update of basis (re-read k slices from smem)
#pragma unroll
        for (int r = 0; r < RR; r++) {
            float4 kk4 = *(const float4*)&ksm[wl][cur][r][lane * 4];
            Wr.x = fmaf(-ee[r], kk4.x, Wr.x);
            Wr.y = fmaf(-ee[r], kk4.y, Wr.y);
            Wr.z = fmaf(-ee[r], kk4.z, Wr.z);
            Wr.w = fmaf(-ee[r], kk4.w, Wr.w);
        }

        // rotate v buffers
#pragma unroll
        for (int r = 0; r < RR; r++) { vc[r] = vn1[r]; vn1[r] = vn2[r]; }
    }

    *(float4*)(wfinal + (size_t)(b * HD + i) * HD + lane * 4) = Wr;
}

// ---------------------------------------------------------------------------
// ypass: per (chunk c, batch b) CTA reconstructs
//   Y = Q_c * W0^T - eta * tril_strict(Q_c K_c^T) * E_c   (fp32 output)
// ---------------------------------------------------------------------------
__global__ __launch_bounds__(256) void ypass_kernel(const float* __restrict__ lr)
{
    const int c = blockIdx.x, b = blockIdx.y;
    const size_t base = ((size_t)b * SS + (size_t)c * CC) * HD;
    const float* Q  = g_q + base;
    const float* K  = g_k + base;
    const float* E  = g_e + base;
    const float* W0 = g_wsnap + (size_t)(b * NCH + c) * HD * HD;
    float* Y = g_y + base;
    const float eta = __ldg(lr);

    __shared__ float As2[CC][68];
    __shared__ float St[8][132];
    __shared__ float Qt[8][68];

    const int tid = threadIdx.x;
    const int ty = tid >> 4;
    const int tx = tid & 15;

    // ---- Phase A: A = Q K^T  (64x64, K=128) ----
    {
        float acc[4][4];
#pragma unroll
        for (int i = 0; i < 4; i++)
#pragma unroll
            for (int j = 0; j < 4; j++) acc[i][j] = 0.f;

        for (int h0 = 0; h0 < HD; h0 += 8) {
            __syncthreads();
            if (tid < 128) {
                const int t = tid >> 1, hh = (tid & 1) << 2;
                float4 qv = *(const float4*)(Q + (size_t)t * HD + h0 + hh);
                Qt[hh + 0][t] = qv.x; Qt[hh + 1][t] = qv.y;
                Qt[hh + 2][t] = qv.z; Qt[hh + 3][t] = qv.w;
            } else {
                const int m = tid - 128;
                const int s = m >> 1, hh = (m & 1) << 2;
                float4 kv = *(const float4*)(K + (size_t)s * HD + h0 + hh);
                St[hh + 0][s] = kv.x; St[hh + 1][s] = kv.y;
                St[hh + 2][s] = kv.z; St[hh + 3][s] = kv.w;
            }
            __syncthreads();
#pragma unroll
            for (int hh = 0; hh < 8; hh++) {
                float a[4], bb[4];
#pragma unroll
                for (int i = 0; i < 4; i++) a[i]  = Qt[hh][ty * 4 + i];
#pragma unroll
                for (int j = 0; j < 4; j++) bb[j] = St[hh][tx * 4 + j];
#pragma unroll
                for (int i = 0; i < 4; i++)
#pragma unroll
                    for (int j = 0; j < 4; j++) acc[i][j] = fmaf(a[i], bb[j], acc[i][j]);
            }
        }
        __syncthreads();
#pragma unroll
        for (int i = 0; i < 4; i++)
#pragma unroll
            for (int j = 0; j < 4; j++) {
                const int t = ty * 4 + i, s = tx * 4 + j;
                As2[t][s] = (s < t) ? (-eta * acc[i][j]) : 0.f;
            }
        __syncthreads();
    }

    // ---- Phase B: Y = Q W0^T + As2 * E  (64x128) ----
    float acc[4][8];
#pragma unroll
    for (int i = 0; i < 4; i++)
#pragma unroll
        for (int j = 0; j < 8; j++) acc[i][j] = 0.f;

    for (int h0 = 0; h0 < HD; h0 += 8) {
        __syncthreads();
        if (tid < 128) {
            const int t = tid >> 1, hh = (tid & 1) << 2;
            float4 qv = *(const float4*)(Q + (size_t)t * HD + h0 + hh);
            Qt[hh + 0][t] = qv.x; Qt[hh + 1][t] = qv.y;
            Qt[hh + 2][t] = qv.z; Qt[hh + 3][t] = qv.w;
        }
        {
            const int j = tid >> 1, hh = (tid & 1) << 2;
            float4 wv = *(const float4*)(W0 + (size_t)j * HD + h0 + hh);
            St[hh + 0][j] = wv.x; St[hh + 1][j] = wv.y;
            St[hh + 2][j] = wv.z; St[hh + 3][j] = wv.w;
        }
        __syncthreads();
#pragma unroll
        for (int hh = 0; hh < 8; hh++) {
            float a[4], bb[8];
#pragma unroll
            for (int i = 0; i < 4; i++) a[i]  = Qt[hh][ty * 4 + i];
#pragma unroll
            for (int j = 0; j < 8; j++) bb[j] = St[hh][tx * 8 + j];
#pragma unroll
            for (int i = 0; i < 4; i++)
#pragma unroll
                for (int j = 0; j < 8; j++) acc[i][j] = fmaf(a[i], bb[j], acc[i][j]);
        }
    }

    for (int s0 = 0; s0 < CC; s0 += 8) {
        __syncthreads();
        {
            const int ss = tid >> 5, j4 = (tid & 31) << 2;
            float4 ev = *(const float4*)(E + (size_t)(s0 + ss) * HD + j4);
            *(float4*)&St[ss][j4] = ev;
        }
        __syncthreads();
#pragma unroll
        for (int ss = 0; ss < 8; ss++) {
            float a[4], bb[8];
#pragma unroll
            for (int i = 0; i < 4; i++) a[i]  = As2[ty * 4 + i][s0 + ss];
#pragma unroll
            for (int j = 0; j < 8; j++) bb[j] = St[ss][tx * 8 + j];
#pragma unroll
            for (int i = 0; i < 4; i++)
#pragma unroll
                for (int j = 0; j < 8; j++) acc[i][j] = fmaf(a[i], bb[j], acc[i][j]);
        }
    }

#pragma unroll
    for (int i = 0; i < 4; i++) {
        float* yr = Y + (size_t)(ty * 4 + i) * HD + tx * 8;
        *(float4*)yr       = make_float4(acc[i][0], acc[i][1], acc[i][2], acc[i][3]);
        *(float4*)(yr + 4) = make_float4(acc[i][4], acc[i][5], acc[i][6], acc[i][7]);
    }
}

// ---------------------------------------------------------------------------
// kernel_launch — R12 serial order; ONLY qmma overlaps, and only with the
// scan (the one phase with idle SMs). qmma is gated on an event recorded
// after gram, so it never contends with the fma-ceiling-bound fp32 GEMMs.
// ---------------------------------------------------------------------------
extern "C" void kernel_launch(void* const* d_in, const int* in_sizes, int n_in,
                              void* d_out, int out_size)
{
    const float* x  = (const float*)d_in[0];
    const float* Wq = (const float*)d_in[1];
    const float* Wk = (const float*)d_in[2];
    const float* Wv = (const float*)d_in[3];
    const float* Wo = (const float*)d_in[4];
    const float* lr = (const float*)d_in[5];
    const float* st = (const float*)d_in[6];
    float* out = (float*)d_out;

    static cudaStream_t s2 = nullptr;
    static cudaEvent_t evG = nullptr, evQ = nullptr;
    if (s2 == nullptr) {
        cudaStreamCreateWithFlags(&s2, cudaStreamNonBlocking);
        cudaEventCreateWithFlags(&evG, cudaEventDisableTiming);
        cudaEventCreateWithFlags(&evQ, cudaEventDisableTiming);
    }

    // main stream, serial (R12 order): splits -> kv -> gram
    splitx_kernel<<<(BS * DD / 4) / 256, 256>>>(x);
    splitwq_kernel<<<(DD * HD) / 256, 256>>>(Wq);

    dim3 gkv(1, BS / 128, 2);
    kvgemm_kernel<<<gkv, 256>>>(x, Wk, Wv);

    gram_kernel<<<(BB * SS) / 8, 256>>>();
    cudaEventRecord(evG, 0);

    // s2: qmma runs concurrently with the scan ONLY (starts after gram)
    cudaStreamWaitEvent(s2, evG, 0);
    qmma_kernel<<<BS / 128, 256, 0, s2>>>();
    cudaEventRecord(evQ, s2);

    // main: scan (needs gram + kv, in-stream)
    scan_kernel<<<(BB * HD) / 2, 64>>>(lr, st, out + (size_t)BS * DD);

    // main: ypass needs q (from s2) + e/wsnap (in-stream)
    cudaStreamWaitEvent(0, evQ, 0);
    dim3 gy(NCH, BB);
    ypass_kernel<<<gy, 256>>>(lr);

    // Output projection in fp32 (y magnitude is unbounded; fp16 unsafe here)
    dim3 gout(DD / 128, BS / 128);
    outgemm_kernel<<<gout, 256>>>(Wo, out);
}

// round 15
// speedup vs baseline: 1.2600x; 1.2600x over previous
#include <cuda_runtime.h>
#include <cuda_fp16.h>

// Problem constants (fixed shapes from reference)
#define BB 4
#define SS 4096
#define DD 1024
#define HD 128
#define BS (BB*SS)   // 16384 rows
#define RR 16        // scan lookahead block size
#define NBLK (SS/RR) // 256
#define CC 64        // chunk size for y reconstruction
#define NCH (SS/CC)

// ---------------------------------------------------------------------------
// Scratch (device globals; no allocation allowed in kernel_launch)
// ---------------------------------------------------------------------------
__device__ float g_q[BB*SS*HD];
__device__ float g_k[BB*SS*HD];
__device__ float g_v[BB*SS*HD];
__device__ float g_y[BB*SS*HD];
__device__ float g_e[BB*SS*HD];
__device__ float g_gram16[BB*SS*16];      // per (b,t): G1..G15, pad; Gd = k_{t-d}.k_t
__device__ float g_wsnap[BB*NCH*HD*HD];   // W at chunk starts

// fp16-split Wq (transposed); x is converted in-kernel inside qmma
__device__ __half g_wqh[HD*DD], g_wql[HD*DD];   // Wq^T [HD][DD]

__device__ __forceinline__ float dot4(float4 a, float4 b) {
    return fmaf(a.x, b.x, fmaf(a.y, b.y, fmaf(a.z, b.z, a.w * b.w)));
}

// ---------------------------------------------------------------------------
// splitwq: transpose + split Wq into fp16 hi/lo
// ---------------------------------------------------------------------------
__global__ __launch_bounds__(256) void splitwq_kernel(const float* __restrict__ Wq)
{
    const int r = blockIdx.x * blockDim.x + threadIdx.x;   // 0 .. DD*HD-1
    const int d = r >> 7, h = r & 127;
    const float f = Wq[r];
    __half hi = __float2half_rn(f);
    __half lo = __float2half_rn(f - __half2float(hi));
    g_wqh[h * DD + d] = hi;
    g_wql[h * DD + d] = lo;
}

// ---------------------------------------------------------------------------
// fp16-split tensor-core GEMM (3-term): q = x * Wq^T, x converted in-kernel.
// CTA tile 128x128, K-step 32, 8 warps (2x4), warp tile 64x32, m16n8k16.
// ---------------------------------------------------------------------------
__device__ __forceinline__ void mma16816(float* c, const unsigned* a, const unsigned* b)
{
    asm volatile(
        "mma.sync.aligned.m16n8k16.row.col.f32.f16.f16.f32 "
        "{%0,%1,%2,%3},{%4,%5,%6,%7},{%8,%9},{%0,%1,%2,%3};"
        : "+f"(c[0]), "+f"(c[1]), "+f"(c[2]), "+f"(c[3])
        : "r"(a[0]), "r"(a[1]), "r"(a[2]), "r"(a[3]), "r"(b[0]), "r"(b[1]));
}

// convert 8 floats (two float4) -> int4 of hi half2s + int4 of lo half2s
__device__ __forceinline__ void cvt8_split(float4 a, float4 b, int4& hi, int4& lo)
{
    __half2 h[4], l[4];
    h[0] = __floats2half2_rn(a.x, a.y);
    h[1] = __floats2half2_rn(a.z, a.w);
    h[2] = __floats2half2_rn(b.x, b.y);
    h[3] = __floats2half2_rn(b.z, b.w);
    l[0] = __floats2half2_rn(a.x - __half2float(__low2half(h[0])),
                             a.y - __half2float(__high2half(h[0])));
    l[1] = __floats2half2_rn(a.z - __half2float(__low2half(h[1])),
                             a.w - __half2float(__high2half(h[1])));
    l[2] = __floats2half2_rn(b.x - __half2float(__low2half(h[2])),
                             b.y - __half2float(__high2half(h[2])));
    l[3] = __floats2half2_rn(b.z - __half2float(__low2half(h[3])),
                             b.w - __half2float(__high2half(h[3])));
    hi = *(int4*)&h[0];
    lo = *(int4*)&l[0];
}

__global__ __launch_bounds__(256) void qmma_kernel(const float* __restrict__ x)
{
    __shared__ unsigned AsH[128*20], AsL[128*20], BsH[128*20], BsL[128*20];

    const int bm = blockIdx.x;
    const int N = HD, K = DD;

    const int t = threadIdx.x;
    const int lane = t & 31, wid = t >> 5;
    const int g = lane >> 2, tg = lane & 3;
    const int warpM = wid >> 2, warpN = wid & 3;

    const int lr = t >> 1, lc = t & 1;
    const float* aPf = x + (size_t)(bm * 128 + lr) * K + lc * 16;
    const __half* bPh = g_wqh + (size_t)lr * K + lc * 16;
    const __half* bPl = g_wql + (size_t)lr * K + lc * 16;
    const int sts = lr * 20 + lc * 8;

    float c[4][4][4];
#pragma unroll
    for (int mt = 0; mt < 4; mt++)
#pragma unroll
        for (int nt = 0; nt < 4; nt++)
#pragma unroll
            for (int j = 0; j < 4; j++) c[mt][nt][j] = 0.f;

    // preload tile 0
    float4 fa0 = *(const float4*)(aPf + 0);
    float4 fa1 = *(const float4*)(aPf + 4);
    float4 fa2 = *(const float4*)(aPf + 8);
    float4 fa3 = *(const float4*)(aPf + 12);
    int4 rb0  = *(const int4*)bPh;       int4 rb1  = *(const int4*)(bPh + 8);
    int4 rbl0 = *(const int4*)bPl;       int4 rbl1 = *(const int4*)(bPl + 8);
    {
        int4 h0, l0, h1, l1;
        cvt8_split(fa0, fa1, h0, l0);
        cvt8_split(fa2, fa3, h1, l1);
        *(int4*)&AsH[sts] = h0;   *(int4*)&AsH[sts + 4] = h1;
        *(int4*)&AsL[sts] = l0;   *(int4*)&AsL[sts + 4] = l1;
    }
    *(int4*)&BsH[sts] = rb0;   *(int4*)&BsH[sts + 4] = rb1;
    *(int4*)&BsL[sts] = rbl0;  *(int4*)&BsL[sts + 4] = rbl1;
    __syncthreads();

    const int KT = K / 32;
    for (int kt = 0; kt < KT; kt++) {
        if (kt + 1 < KT) {
            const int o = (kt + 1) * 32;
            fa0 = *(const float4*)(aPf + o);      fa1 = *(const float4*)(aPf + o + 4);
            fa2 = *(const float4*)(aPf + o + 8);  fa3 = *(const float4*)(aPf + o + 12);
            rb0  = *(const int4*)(bPh + o);       rb1  = *(const int4*)(bPh + o + 8);
            rbl0 = *(const int4*)(bPl + o);       rbl1 = *(const int4*)(bPl + o + 8);
        }
#pragma unroll
        for (int s = 0; s < 2; s++) {
            unsigned aH[4][4], aL[4][4], bH[4][2], bL[4][2];
#pragma unroll
            for (int mt = 0; mt < 4; mt++) {
                const int r0 = (warpM * 64 + mt * 16 + g) * 20 + s * 8 + tg;
                aH[mt][0] = AsH[r0];       aH[mt][1] = AsH[r0 + 160];
                aH[mt][2] = AsH[r0 + 4];   aH[mt][3] = AsH[r0 + 164];
                aL[mt][0] = AsL[r0];       aL[mt][1] = AsL[r0 + 160];
                aL[mt][2] = AsL[r0 + 4];   aL[mt][3] = AsL[r0 + 164];
            }
#pragma unroll
            for (int nt = 0; nt < 4; nt++) {
                const int n0 = (warpN * 32 + nt * 8 + g) * 20 + s * 8 + tg;
                bH[nt][0] = BsH[n0];  bH[nt][1] = BsH[n0 + 4];
                bL[nt][0] = BsL[n0];  bL[nt][1] = BsL[n0 + 4];
            }
#pragma unroll
            for (int mt = 0; mt < 4; mt++)
#pragma unroll
                for (int nt = 0; nt < 4; nt++) {
                    mma16816(c[mt][nt], aH[mt], bH[nt]);
                    mma16816(c[mt][nt], aH[mt], bL[nt]);
                    mma16816(c[mt][nt], aL[mt], bH[nt]);
                }
        }
        __syncthreads();
        if (kt + 1 < KT) {
            int4 h0, l0, h1, l1;
            cvt8_split(fa0, fa1, h0, l0);
            cvt8_split(fa2, fa3, h1, l1);
            *(int4*)&AsH[sts] = h0;   *(int4*)&AsH[sts + 4] = h1;
            *(int4*)&AsL[sts] = l0;   *(int4*)&AsL[sts + 4] = l1;
            *(int4*)&BsH[sts] = rb0;   *(int4*)&BsH[sts + 4] = rb1;
            *(int4*)&BsL[sts] = rbl0;  *(int4*)&BsL[sts + 4] = rbl1;
            __syncthreads();
        }
    }

#pragma unroll
    for (int mt = 0; mt < 4; mt++)
#pragma unroll
        for (int nt = 0; nt < 4; nt++) {
            const int row = bm * 128 + warpM * 64 + mt * 16 + g;
            const int col = warpN * 32 + nt * 8 + 2 * tg;
            *(float2*)&g_q[(size_t)row * N + col]       = make_float2(c[mt][nt][0], c[mt][nt][1]);
            *(float2*)&g_q[(size_t)(row + 8) * N + col] = make_float2(c[mt][nt][2], c[mt][nt][3]);
        }
}

// ---------------------------------------------------------------------------
// fp32 SGEMM body (known good): C = A[M,K]*B[K,N]
// ---------------------------------------------------------------------------
__device__ __forceinline__ void sgemm_body(
    const float* __restrict__ A, const float* __restrict__ Bm,
    float* __restrict__ C, int M, int N, int K, int bx, int by)
{
    __shared__ float As[8][128];
    __shared__ float Bs[8][132];

    const int tid = threadIdx.x;
    const int ty = tid >> 4;
    const int tx = tid & 15;
    const int a_r = tid >> 1;
    const int a_c = (tid & 1) << 2;
    const int b_r = tid >> 5;
    const int b_c = (tid & 31) << 2;

    const float* Ab = A + (size_t)by * 128 * K;
    const float* Bb = Bm + bx * 128;

    float acc[8][8];
#pragma unroll
    for (int i = 0; i < 8; i++)
#pragma unroll
        for (int j = 0; j < 8; j++) acc[i][j] = 0.f;

    for (int k0 = 0; k0 < K; k0 += 8) {
        float4 av = *(const float4*)(Ab + (size_t)a_r * K + k0 + a_c);
        float4 bv = *(const float4*)(Bb + (size_t)(k0 + b_r) * N + b_c);
        __syncthreads();
        As[a_c + 0][a_r] = av.x;
        As[a_c + 1][a_r] = av.y;
        As[a_c + 2][a_r] = av.z;
        As[a_c + 3][a_r] = av.w;
        *(float4*)&Bs[b_r][b_c] = bv;
        __syncthreads();
#pragma unroll
        for (int kk = 0; kk < 8; kk++) {
            float a[8], b[8];
#pragma unroll
            for (int i = 0; i < 8; i++) a[i] = As[kk][ty * 8 + i];
#pragma unroll
            for (int j = 0; j < 8; j++) b[j] = Bs[kk][tx * 8 + j];
#pragma unroll
            for (int i = 0; i < 8; i++)
#pragma unroll
                for (int j = 0; j < 8; j++) acc[i][j] = fmaf(a[i], b[j], acc[i][j]);
        }
    }

    float* Cb = C + (size_t)(by * 128 + ty * 8) * N + bx * 128 + tx * 8;
#pragma unroll
    for (int i = 0; i < 8; i++) {
        *(float4*)(Cb + (size_t)i * N)     = make_float4(acc[i][0], acc[i][1], acc[i][2], acc[i][3]);
        *(float4*)(Cb + (size_t)i * N + 4) = make_float4(acc[i][4], acc[i][5], acc[i][6], acc[i][7]);
    }
}

// Fused K,V projections in fp32 (recurrence-sensitive operands)
__global__ __launch_bounds__(256) void kvgemm_kernel(
    const float* __restrict__ x, const float* __restrict__ Wk,
    const float* __restrict__ Wv)
{
    const float* Bm = (blockIdx.z == 0) ? Wk : Wv;
    float* C = (blockIdx.z == 0) ? g_k : g_v;
    sgemm_body(x, Bm, C, BS, HD, DD, 0, blockIdx.y);
}

__global__ __launch_bounds__(256) void outgemm_kernel(
    const float* __restrict__ Wo, float* __restrict__ out)
{
    sgemm_body(g_y, Wo, out, BS, DD, HD, blockIdx.x, blockIdx.y);
}

// ---------------------------------------------------------------------------
// Gram kernel: one warp per (b,t): G_d[t] = k_{t-d}.k_t for d=1..15
// ---------------------------------------------------------------------------
__global__ __launch_bounds__(256) void gram_kernel()
{
    const int w = (blockIdx.x * blockDim.x + threadIdx.x) >> 5;  // b*SS + t
    const int lane = threadIdx.x & 31;
    if (w >= BB * SS) return;
    const int t = w & (SS - 1);

    float4 kc = *(const float4*)(g_k + (size_t)w * HD + lane * 4);
    float dd[15];
#pragma unroll
    for (int d2 = 1; d2 <= 15; d2++) {
        float4 kd = make_float4(0.f, 0.f, 0.f, 0.f);
        if (t >= d2) kd = *(const float4*)(g_k + (size_t)(w - d2) * HD + lane * 4);
        dd[d2 - 1] = dot4(kd, kc);
    }
#pragma unroll
    for (int s = 16; s; s >>= 1) {
#pragma unroll
        for (int j = 0; j < 15; j++) dd[j] += __shfl_xor_sync(~0u, dd[j], s);
    }
    if (lane == 0) {
        float* gp = g_gram16 + (size_t)w * 16;
        *(float4*)(gp)      = make_float4(dd[0],  dd[1],  dd[2],  dd[3]);
        *(float4*)(gp + 4)  = make_float4(dd[4],  dd[5],  dd[6],  dd[7]);
        *(float4*)(gp + 8)  = make_float4(dd[8],  dd[9],  dd[10], dd[11]);
        *(float4*)(gp + 12) = make_float4(dd[12], dd[13], dd[14], 0.f);
    }
}

// ---------------------------------------------------------------------------
// Scan, R=16: ONE CTA (2 warps, 64 threads) per (batch, W-row). Warp w owns
// columns [64w, 64w+64) as float2/lane. Half-dots + butterfly per warp, the
// halves combined through parity-buffered smem + __syncthreads; the scalar
// recurrence runs redundantly in both warps. k streamed via 2-stage cp.async
// (8B self-copied chunks, no extra barrier); gram double-buffered in smem.
// ---------------------------------------------------------------------------
__device__ __forceinline__ void cp_async8(unsigned smem_addr, const void* gptr)
{
    asm volatile("cp.async.ca.shared.global [%0], [%1], 8;"
                 :: "r"(smem_addr), "l"(gptr));
}
__device__ __forceinline__ void cp_commit() {
    asm volatile("cp.async.commit_group;");
}
__device__ __forceinline__ void cp_wait1() {
    asm volatile("cp.async.wait_group 1;");
}

__global__ __launch_bounds__(64) void scan_kernel(
    const float* __restrict__ lr, const float* __restrict__ state,
    float* __restrict__ wfinal)
{
    __shared__ float  ksm[2][RR][HD];    // 16KB, shared by both warps
    __shared__ float4 gwbuf[2][64];      // gram double buffer (16 floats per t)
    __shared__ float  pd[2][2][RR];      // [parity][warp][r] partial dots

    const int tid = threadIdx.x;
    const int wl = tid >> 5;
    const int lane = tid & 31;
    const int b = blockIdx.x >> 7;
    const int i = blockIdx.x & 127;
    const int col = wl * 64 + lane * 2;       // this thread's 2 columns
    const float eta = __ldg(lr);

    const float* kp = g_k + (size_t)b * SS * HD;
    const float* vp = g_v + (size_t)b * SS * HD + i;
    const float4* gp4 = (const float4*)(g_gram16 + (size_t)b * SS * 16);
    float* ep = g_e + (size_t)b * SS * HD + i;

    float2 Wr = *(const float2*)(state + (size_t)(b * HD + i) * HD + col);

    // smem byte address of this thread's 8B slice in stage 0, row 0
    unsigned kbase = (unsigned)__cvta_generic_to_shared(&ksm[0][0][col]);
    const unsigned KROW = HD * 4;             // 512B per row
    const unsigned KSTAGE = RR * KROW;        // 8KB per stage

    float vc[RR], vn1[RR], vn2[RR];
    // prologue: stage0 <- block0 (each thread copies exactly what it reads)
#pragma unroll
    for (int r = 0; r < RR; r++)
        cp_async8(kbase + r * KROW, kp + (size_t)r * HD + col);
    cp_commit();
#pragma unroll
    for (int r = 0; r < RR; r++) {
        vc[r]  = vp[(size_t)r * HD];
        vn1[r] = vp[(size_t)(RR + r) * HD];
    }
    gwbuf[0][tid] = gp4[tid];
    __syncthreads();

    for (int blk = 0; blk < NBLK; blk++) {
        const int T = blk * RR;
        const int cur = blk & 1;

        // chunk-start snapshot (Wr == W_{T-1}; CC/RR = 4)
        if ((blk & 3) == 0) {
            const int c = blk >> 2;
            *(float2*)(g_wsnap + ((size_t)((b * NCH + c) * HD + i)) * HD + col) = Wr;
        }

        // prefetch k for blk+1 into stage cur^1
        const int T1 = ((blk + 1 < NBLK) ? (blk + 1) : (NBLK - 1)) * RR;
#pragma unroll
        for (int r = 0; r < RR; r++)
            cp_async8(kbase + (cur ^ 1) * KSTAGE + r * KROW,
                      kp + (size_t)(T1 + r) * HD + col);
        cp_commit();

        // v prefetch depth 2 (uniform loads)
        const int T2 = ((blk + 2 < NBLK) ? (blk + 2) : (NBLK - 1)) * RR;
#pragma unroll
        for (int r = 0; r < RR; r++) vn2[r] = vp[(size_t)(T2 + r) * HD];

        // gram prefetch depth 1 (one float4 per thread)
        float4 g4 = gp4[(size_t)T1 * 4 + tid];

        // wait for this block's k stage (self-copied -> no barrier needed)
        cp_wait1();

        // 16 half-dots over this warp's 64 columns
        float d[RR];
#pragma unroll
        for (int r = 0; r < RR; r++) {
            float2 kk2 = *(const float2*)&ksm[cur][r][col];
            d[r] = fmaf(kk2.x, Wr.x, kk2.y * Wr.y);
        }
        // butterfly: all lanes end up with the warp's half-sum
#pragma unroll
        for (int s = 16; s; s >>= 1) {
#pragma unroll
            for (int j = 0; j < RR; j++) d[j] += __shfl_xor_sync(~0u, d[j], s);
        }
        // publish this warp's half (lane 0, unrolled)
        if (lane == 0) {
#pragma unroll
            for (int r = 0; r < RR; r++) pd[cur][wl][r] = d[r];
        }
        __syncthreads();

        // publish next gram block (write target != any current read target;
        // ordered vs next block's readers by its own __syncthreads)
        gwbuf[cur ^ 1][tid] = g4;

        // combine halves (uniform smem reads -> broadcast)
#pragma unroll
        for (int r = 0; r < RR; r++) d[r] = pd[cur][0][r] + pd[cur][1][r];

        // serial scalar recurrence (redundant in both warps)
        const float* gbuf = (const float*)&gwbuf[cur][0];
        float e[RR], ee[RR];
#pragma unroll
        for (int r = 0; r < RR; r++) {
            float acc = d[r] - vc[r];
#pragma unroll
            for (int dd2 = r; dd2 >= 1; --dd2)
                acc = fmaf(-ee[r - dd2], gbuf[r * 16 + dd2 - 1], acc);
            e[r] = acc;
            ee[r] = eta * acc;
        }

        if (tid == 0) {
#pragma unroll
            for (int r = 0; r < RR; r++) ep[(size_t)(T + r) * HD] = e[r];
        }

        // rank-16 update of this warp's half of the basis row
#pragma unroll
        for (int r = 0; r < RR; r++) {
            float2 kk2 = *(const float2*)&ksm[cur][r][col];
            Wr.x = fmaf(-ee[r], kk2.x, Wr.x);
            Wr.y = fmaf(-ee[r], kk2.y, Wr.y);
        }

        // rotate v buffers
#pragma unroll
        for (int r = 0; r < RR; r++) { vc[r] = vn1[r]; vn1[r] = vn2[r]; }
    }

    *(float2*)(wfinal + (size_t)(b * HD + i) * HD + col) = Wr;
}

// ---------------------------------------------------------------------------
// ypass: per (chunk c, batch b) CTA reconstructs
//   Y = Q_c * W0^T - eta * tril_strict(Q_c K_c^T) * E_c   (fp32 output)
// ---------------------------------------------------------------------------
__global__ __launch_bounds__(256) void ypass_kernel(const float* __restrict__ lr)
{
    const int c = blockIdx.x, b = blockIdx.y;
    const size_t base = ((size_t)b * SS + (size_t)c * CC) * HD;
    const float* Q  = g_q + base;
    const float* K  = g_k + base;
    const float* E  = g_e + base;
    const float* W0 = g_wsnap + (size_t)(b * NCH + c) * HD * HD;
    float* Y = g_y + base;
    const float eta = __ldg(lr);

    __shared__ float As2[CC][68];
    __shared__ float St[8][132];
    __shared__ float Qt[8][68];

    const int tid = threadIdx.x;
    const int ty = tid >> 4;
    const int tx = tid & 15;

    // ---- Phase A: A = Q K^T  (64x64, K=128) ----
    {
        float acc[4][4];
#pragma unroll
        for (int i = 0; i < 4; i++)
#pragma unroll
            for (int j = 0; j < 4; j++) acc[i][j] = 0.f;

        for (int h0 = 0; h0 < HD; h0 += 8) {
            __syncthreads();
            if (tid < 128) {
                const int t = tid >> 1, hh = (tid & 1) << 2;
                float4 qv = *(const float4*)(Q + (size_t)t * HD + h0 + hh);
                Qt[hh + 0][t] = qv.x; Qt[hh + 1][t] = qv.y;
                Qt[hh + 2][t] = qv.z; Qt[hh + 3][t] = qv.w;
            } else {
                const int m = tid - 128;
                const int s = m >> 1, hh = (m & 1) << 2;
                float4 kv = *(const float4*)(K + (size_t)s * HD + h0 + hh);
                St[hh + 0][s] = kv.x; St[hh + 1][s] = kv.y;
                St[hh + 2][s] = kv.z; St[hh + 3][s] = kv.w;
            }
            __syncthreads();
#pragma unroll
            for (int hh = 0; hh < 8; hh++) {
                float a[4], bb[4];
#pragma unroll
                for (int i = 0; i < 4; i++) a[i]  = Qt[hh][ty * 4 + i];
#pragma unroll
                for (int j = 0; j < 4; j++) bb[j] = St[hh][tx * 4 + j];
#pragma unroll
                for (int i = 0; i < 4; i++)
#pragma unroll
                    for (int j = 0; j < 4; j++) acc[i][j] = fmaf(a[i], bb[j], acc[i][j]);
            }
        }
        __syncthreads();
#pragma unroll
        for (int i = 0; i < 4; i++)
#pragma unroll
            for (int j = 0; j < 4; j++) {
                const int t = ty * 4 + i, s = tx * 4 + j;
                As2[t][s] = (s < t) ? (-eta * acc[i][j]) : 0.f;
            }
        __syncthreads();
    }

    // ---- Phase B: Y = Q W0^T + As2 * E  (64x128) ----
    float acc[4][8];
#pragma unroll
    for (int i = 0; i < 4; i++)
#pragma unroll
        for (int j = 0; j < 8; j++) acc[i][j] = 0.f;

    for (int h0 = 0; h0 < HD; h0 += 8) {
        __syncthreads();
        if (tid < 128) {
            const int t = tid >> 1, hh = (tid & 1) << 2;
            float4 qv = *(const float4*)(Q + (size_t)t * HD + h0 + hh);
            Qt[hh + 0][t] = qv.x; Qt[hh + 1][t] = qv.y;
            Qt[hh + 2][t] = qv.z; Qt[hh + 3][t] = qv.w;
        }
        {
            const int j = tid >> 1, hh = (tid & 1) << 2;
            float4 wv = *(const float4*)(W0 + (size_t)j * HD + h0 + hh);
            St[hh + 0][j] = wv.x; St[hh + 1][j] = wv.y;
            St[hh + 2][j] = wv.z; St[hh + 3][j] = wv.w;
        }
        __syncthreads();
#pragma unroll
        for (int hh = 0; hh < 8; hh++) {
            float a[4], bb[8];
#pragma unroll
            for (int i = 0; i < 4; i++) a[i]  = Qt[hh][ty * 4 + i];
#pragma unroll
            for (int j = 0; j < 8; j++) bb[j] = St[hh][tx * 8 + j];
#pragma unroll
            for (int i = 0; i < 4; i++)
#pragma unroll
                for (int j = 0; j < 8; j++) acc[i][j] = fmaf(a[i], bb[j], acc[i][j]);
        }
    }

    for (int s0 = 0; s0 < CC; s0 += 8) {
        __syncthreads();
        {
            const int ss = tid >> 5, j4 = (tid & 31) << 2;
            float4 ev = *(const float4*)(E + (size_t)(s0 + ss) * HD + j4);
            *(float4*)&St[ss][j4] = ev;
        }
        __syncthreads();
#pragma unroll
        for (int ss = 0; ss < 8; ss++) {
            float a[4], bb[8];
#pragma unroll
            for (int i = 0; i < 4; i++) a[i]  = As2[ty * 4 + i][s0 + ss];
#pragma unroll
            for (int j = 0; j < 8; j++) bb[j] = St[ss][tx * 8 + j];
#pragma unroll
            for (int i = 0; i < 4; i++)
#pragma unroll
                for (int j = 0; j < 8; j++) acc[i][j] = fmaf(a[i], bb[j], acc[i][j]);
        }
    }

#pragma unroll
    for (int i = 0; i < 4; i++) {
        float* yr = Y + (size_t)(ty * 4 + i) * HD + tx * 8;
        *(float4*)yr       = make_float4(acc[i][0], acc[i][1], acc[i][2], acc[i][3]);
        *(float4*)(yr + 4) = make_float4(acc[i][4], acc[i][5], acc[i][6], acc[i][7]);
    }
}

// ---------------------------------------------------------------------------
// kernel_launch — strictly serial, single stream (streams measured 2x WORSE
// in this harness's graph replay; R13/R14 evidence).
// ---------------------------------------------------------------------------
extern "C" void kernel_launch(void* const* d_in, const int* in_sizes, int n_in,
                              void* d_out, int out_size)
{
    const float* x  = (const float*)d_in[0];
    const float* Wq = (const float*)d_in[1];
    const float* Wk = (const float*)d_in[2];
    const float* Wv = (const float*)d_in[3];
    const float* Wo = (const float*)d_in[4];
    const float* lr = (const float*)d_in[5];
    const float* st = (const float*)d_in[6];
    float* out = (float*)d_out;

    // Wq transpose+split (x is converted inside qmma)
    splitwq_kernel<<<(DD * HD) / 256, 256>>>(Wq);

    // K,V projections in fp32 (fused)
    dim3 gkv(1, BS / 128, 2);
    kvgemm_kernel<<<gkv, 256>>>(x, Wk, Wv);

    // Q projection on tensor cores (3-term fp16 split, in-kernel x convert)
    qmma_kernel<<<BS / 128, 256>>>(x);

    // Gram scalars (k.k, distances 1..15)
    gram_kernel<<<(BB * SS) / 8, 256>>>();

    // Error scan: one 2-warp CTA per (batch, row)
    scan_kernel<<<BB * HD, 64>>>(lr, st, out + (size_t)BS * DD);

    // Parallel Y reconstruction per chunk (fp32 y)
    dim3 gy(NCH, BB);
    ypass_kernel<<<gy, 256>>>(lr);

    // Output projection in fp32 (y magnitude is unbounded; fp16 unsafe here)
    dim3 gout(DD / 128, BS / 128);
    outgemm_kernel<<<gout, 256>>>(Wo, out);
}

// round 16
// speedup vs baseline: 1.4730x; 1.1691x over previous
#include <cuda_runtime.h>
#include <cuda_fp16.h>

// Problem constants (fixed shapes from reference)
#define BB 4
#define SS 4096
#define DD 1024
#define HD 128
#define BS (BB*SS)   // 16384 rows
#define RR 16        // scan lookahead block size
#define NBLK (SS/RR) // 256
#define CC 64        // chunk size for y reconstruction
#define NCH (SS/CC)

// ---------------------------------------------------------------------------
// Scratch (device globals; no allocation allowed in kernel_launch)
// ---------------------------------------------------------------------------
__device__ float g_q[BB*SS*HD];
__device__ float g_k[BB*SS*HD];
__device__ float g_v[BB*SS*HD];
__device__ float g_y[BB*SS*HD];
__device__ float g_e[BB*SS*HD];
__device__ float g_gram16[BB*SS*16];      // per (b,t): G1..G15, pad; Gd = k_{t-d}.k_t
__device__ float g_wsnap[BB*NCH*HD*HD];   // W at chunk starts

// fp16-split Wq (transposed); x is converted in-kernel inside qmma
__device__ __half g_wqh[HD*DD], g_wql[HD*DD];   // Wq^T [HD][DD]

__device__ __forceinline__ float dot4(float4 a, float4 b) {
    return fmaf(a.x, b.x, fmaf(a.y, b.y, fmaf(a.z, b.z, a.w * b.w)));
}

// ---------------------------------------------------------------------------
// splitwq: transpose + split Wq into fp16 hi/lo
// ---------------------------------------------------------------------------
__global__ __launch_bounds__(256) void splitwq_kernel(const float* __restrict__ Wq)
{
    const int r = blockIdx.x * blockDim.x + threadIdx.x;   // 0 .. DD*HD-1
    const int d = r >> 7, h = r & 127;
    const float f = Wq[r];
    __half hi = __float2half_rn(f);
    __half lo = __float2half_rn(f - __half2float(hi));
    g_wqh[h * DD + d] = hi;
    g_wql[h * DD + d] = lo;
}

// ---------------------------------------------------------------------------
// fp16-split tensor-core GEMM (3-term): q = x * Wq^T, x converted in-kernel.
// CTA tile 128x128, K-step 32, 8 warps (2x4), warp tile 64x32, m16n8k16.
// ---------------------------------------------------------------------------
__device__ __forceinline__ void mma16816(float* c, const unsigned* a, const unsigned* b)
{
    asm volatile(
        "mma.sync.aligned.m16n8k16.row.col.f32.f16.f16.f32 "
        "{%0,%1,%2,%3},{%4,%5,%6,%7},{%8,%9},{%0,%1,%2,%3};"
        : "+f"(c[0]), "+f"(c[1]), "+f"(c[2]), "+f"(c[3])
        : "r"(a[0]), "r"(a[1]), "r"(a[2]), "r"(a[3]), "r"(b[0]), "r"(b[1]));
}

// convert 8 floats (two float4) -> int4 of hi half2s + int4 of lo half2s
__device__ __forceinline__ void cvt8_split(float4 a, float4 b, int4& hi, int4& lo)
{
    __half2 h[4], l[4];
    h[0] = __floats2half2_rn(a.x, a.y);
    h[1] = __floats2half2_rn(a.z, a.w);
    h[2] = __floats2half2_rn(b.x, b.y);
    h[3] = __floats2half2_rn(b.z, b.w);
    l[0] = __floats2half2_rn(a.x - __half2float(__low2half(h[0])),
                             a.y - __half2float(__high2half(h[0])));
    l[1] = __floats2half2_rn(a.z - __half2float(__low2half(h[1])),
                             a.w - __half2float(__high2half(h[1])));
    l[2] = __floats2half2_rn(b.x - __half2float(__low2half(h[2])),
                             b.y - __half2float(__high2half(h[2])));
    l[3] = __floats2half2_rn(b.z - __half2float(__low2half(h[3])),
                             b.w - __half2float(__high2half(h[3])));
    hi = *(int4*)&h[0];
    lo = *(int4*)&l[0];
}

__global__ __launch_bounds__(256) void qmma_kernel(const float* __restrict__ x)
{
    __shared__ unsigned AsH[128*20], AsL[128*20], BsH[128*20], BsL[128*20];

    const int bm = blockIdx.x;
    const int N = HD, K = DD;

    const int t = threadIdx.x;
    const int lane = t & 31, wid = t >> 5;
    const int g = lane >> 2, tg = lane & 3;
    const int warpM = wid >> 2, warpN = wid & 3;

    const int lr = t >> 1, lc = t & 1;
    const float* aPf = x + (size_t)(bm * 128 + lr) * K + lc * 16;
    const __half* bPh = g_wqh + (size_t)lr * K + lc * 16;
    const __half* bPl = g_wql + (size_t)lr * K + lc * 16;
    const int sts = lr * 20 + lc * 8;

    float c[4][4][4];
#pragma unroll
    for (int mt = 0; mt < 4; mt++)
#pragma unroll
        for (int nt = 0; nt < 4; nt++)
#pragma unroll
            for (int j = 0; j < 4; j++) c[mt][nt][j] = 0.f;

    // preload tile 0
    float4 fa0 = *(const float4*)(aPf + 0);
    float4 fa1 = *(const float4*)(aPf + 4);
    float4 fa2 = *(const float4*)(aPf + 8);
    float4 fa3 = *(const float4*)(aPf + 12);
    int4 rb0  = *(const int4*)bPh;       int4 rb1  = *(const int4*)(bPh + 8);
    int4 rbl0 = *(const int4*)bPl;       int4 rbl1 = *(const int4*)(bPl + 8);
    {
        int4 h0, l0, h1, l1;
        cvt8_split(fa0, fa1, h0, l0);
        cvt8_split(fa2, fa3, h1, l1);
        *(int4*)&AsH[sts] = h0;   *(int4*)&AsH[sts + 4] = h1;
        *(int4*)&AsL[sts] = l0;   *(int4*)&AsL[sts + 4] = l1;
    }
    *(int4*)&BsH[sts] = rb0;   *(int4*)&BsH[sts + 4] = rb1;
    *(int4*)&BsL[sts] = rbl0;  *(int4*)&BsL[sts + 4] = rbl1;
    __syncthreads();

    const int KT = K / 32;
    for (int kt = 0; kt < KT; kt++) {
        if (kt + 1 < KT) {
            const int o = (kt + 1) * 32;
            fa0 = *(const float4*)(aPf + o);      fa1 = *(const float4*)(aPf + o + 4);
            fa2 = *(const float4*)(aPf + o + 8);  fa3 = *(const float4*)(aPf + o + 12);
            rb0  = *(const int4*)(bPh + o);       rb1  = *(const int4*)(bPh + o + 8);
            rbl0 = *(const int4*)(bPl + o);       rbl1 = *(const int4*)(bPl + o + 8);
        }
#pragma unroll
        for (int s = 0; s < 2; s++) {
            unsigned aH[4][4], aL[4][4], bH[4][2], bL[4][2];
#pragma unroll
            for (int mt = 0; mt < 4; mt++) {
                const int r0 = (warpM * 64 + mt * 16 + g) * 20 + s * 8 + tg;
                aH[mt][0] = AsH[r0];       aH[mt][1] = AsH[r0 + 160];
                aH[mt][2] = AsH[r0 + 4];   aH[mt][3] = AsH[r0 + 164];
                aL[mt][0] = AsL[r0];       aL[mt][1] = AsL[r0 + 160];
                aL[mt][2] = AsL[r0 + 4];   aL[mt][3] = AsL[r0 + 164];
            }
#pragma unroll
            for (int nt = 0; nt < 4; nt++) {
                const int n0 = (warpN * 32 + nt * 8 + g) * 20 + s * 8 + tg;
                bH[nt][0] = BsH[n0];  bH[nt][1] = BsH[n0 + 4];
                bL[nt][0] = BsL[n0];  bL[nt][1] = BsL[n0 + 4];
            }
#pragma unroll
            for (int mt = 0; mt < 4; mt++)
#pragma unroll
                for (int nt = 0; nt < 4; nt++) {
                    mma16816(c[mt][nt], aH[mt], bH[nt]);
                    mma16816(c[mt][nt], aH[mt], bL[nt]);
                    mma16816(c[mt][nt], aL[mt], bH[nt]);
                }
        }
        __syncthreads();
        if (kt + 1 < KT) {
            int4 h0, l0, h1, l1;
            cvt8_split(fa0, fa1, h0, l0);
            cvt8_split(fa2, fa3, h1, l1);
            *(int4*)&AsH[sts] = h0;   *(int4*)&AsH[sts + 4] = h1;
            *(int4*)&AsL[sts] = l0;   *(int4*)&AsL[sts + 4] = l1;
            *(int4*)&BsH[sts] = rb0;   *(int4*)&BsH[sts + 4] = rb1;
            *(int4*)&BsL[sts] = rbl0;  *(int4*)&BsL[sts + 4] = rbl1;
            __syncthreads();
        }
    }

#pragma unroll
    for (int mt = 0; mt < 4; mt++)
#pragma unroll
        for (int nt = 0; nt < 4; nt++) {
            const int row = bm * 128 + warpM * 64 + mt * 16 + g;
            const int col = warpN * 32 + nt * 8 + 2 * tg;
            *(float2*)&g_q[(size_t)row * N + col]       = make_float2(c[mt][nt][0], c[mt][nt][1]);
            *(float2*)&g_q[(size_t)(row + 8) * N + col] = make_float2(c[mt][nt][2], c[mt][nt][3]);
        }
}

// ---------------------------------------------------------------------------
// fp32 SGEMM body (known good): C = A[M,K]*B[K,N]
// ---------------------------------------------------------------------------
__device__ __forceinline__ void sgemm_body(
    const float* __restrict__ A, const float* __restrict__ Bm,
    float* __restrict__ C, int M, int N, int K, int bx, int by)
{
    __shared__ float As[8][128];
    __shared__ float Bs[8][132];

    const int tid = threadIdx.x;
    const int ty = tid >> 4;
    const int tx = tid & 15;
    const int a_r = tid >> 1;
    const int a_c = (tid & 1) << 2;
    const int b_r = tid >> 5;
    const int b_c = (tid & 31) << 2;

    const float* Ab = A + (size_t)by * 128 * K;
    const float* Bb = Bm + bx * 128;

    float acc[8][8];
#pragma unroll
    for (int i = 0; i < 8; i++)
#pragma unroll
        for (int j = 0; j < 8; j++) acc[i][j] = 0.f;

    for (int k0 = 0; k0 < K; k0 += 8) {
        float4 av = *(const float4*)(Ab + (size_t)a_r * K + k0 + a_c);
        float4 bv = *(const float4*)(Bb + (size_t)(k0 + b_r) * N + b_c);
        __syncthreads();
        As[a_c + 0][a_r] = av.x;
        As[a_c + 1][a_r] = av.y;
        As[a_c + 2][a_r] = av.z;
        As[a_c + 3][a_r] = av.w;
        *(float4*)&Bs[b_r][b_c] = bv;
        __syncthreads();
#pragma unroll
        for (int kk = 0; kk < 8; kk++) {
            float a[8], b[8];
#pragma unroll
            for (int i = 0; i < 8; i++) a[i] = As[kk][ty * 8 + i];
#pragma unroll
            for (int j = 0; j < 8; j++) b[j] = Bs[kk][tx * 8 + j];
#pragma unroll
            for (int i = 0; i < 8; i++)
#pragma unroll
                for (int j = 0; j < 8; j++) acc[i][j] = fmaf(a[i], b[j], acc[i][j]);
        }
    }

    float* Cb = C + (size_t)(by * 128 + ty * 8) * N + bx * 128 + tx * 8;
#pragma unroll
    for (int i = 0; i < 8; i++) {
        *(float4*)(Cb + (size_t)i * N)     = make_float4(acc[i][0], acc[i][1], acc[i][2], acc[i][3]);
        *(float4*)(Cb + (size_t)i * N + 4) = make_float4(acc[i][4], acc[i][5], acc[i][6], acc[i][7]);
    }
}

// Fused K,V projections in fp32 (recurrence-sensitive operands)
__global__ __launch_bounds__(256) void kvgemm_kernel(
    const float* __restrict__ x, const float* __restrict__ Wk,
    const float* __restrict__ Wv)
{
    const float* Bm = (blockIdx.z == 0) ? Wk : Wv;
    float* C = (blockIdx.z == 0) ? g_k : g_v;
    sgemm_body(x, Bm, C, BS, HD, DD, 0, blockIdx.y);
}

__global__ __launch_bounds__(256) void outgemm_kernel(
    const float* __restrict__ Wo, float* __restrict__ out)
{
    sgemm_body(g_y, Wo, out, BS, DD, HD, blockIdx.x, blockIdx.y);
}

// ---------------------------------------------------------------------------
// Gram kernel: one warp per (b,t): G_d[t] = k_{t-d}.k_t for d=1..15
// ---------------------------------------------------------------------------
__global__ __launch_bounds__(256) void gram_kernel()
{
    const int w = (blockIdx.x * blockDim.x + threadIdx.x) >> 5;  // b*SS + t
    const int lane = threadIdx.x & 31;
    if (w >= BB * SS) return;
    const int t = w & (SS - 1);

    float4 kc = *(const float4*)(g_k + (size_t)w * HD + lane * 4);
    float dd[15];
#pragma unroll
    for (int d2 = 1; d2 <= 15; d2++) {
        float4 kd = make_float4(0.f, 0.f, 0.f, 0.f);
        if (t >= d2) kd = *(const float4*)(g_k + (size_t)(w - d2) * HD + lane * 4);
        dd[d2 - 1] = dot4(kd, kc);
    }
#pragma unroll
    for (int s = 16; s; s >>= 1) {
#pragma unroll
        for (int j = 0; j < 15; j++) dd[j] += __shfl_xor_sync(~0u, dd[j], s);
    }
    if (lane == 0) {
        float* gp = g_gram16 + (size_t)w * 16;
        *(float4*)(gp)      = make_float4(dd[0],  dd[1],  dd[2],  dd[3]);
        *(float4*)(gp + 4)  = make_float4(dd[4],  dd[5],  dd[6],  dd[7]);
        *(float4*)(gp + 8)  = make_float4(dd[8],  dd[9],  dd[10], dd[11]);
        *(float4*)(gp + 12) = make_float4(dd[12], dd[13], dd[14], 0.f);
    }
}

// ---------------------------------------------------------------------------
// Blocked-lookahead error scan, R=16 (R12 known-good version). k via 2-stage
// cp.async smem pipeline (depth-1 prefetch, wait_group 1); v depth-2 register
// prefetch; Gram via smem double buffer. One warp per (batch, W-row).
// ---------------------------------------------------------------------------
__device__ __forceinline__ void cp_async16(unsigned smem_addr, const void* gptr)
{
    asm volatile("cp.async.cg.shared.global [%0], [%1], 16;"
                 :: "r"(smem_addr), "l"(gptr));
}
__device__ __forceinline__ void cp_commit() {
    asm volatile("cp.async.commit_group;");
}
__device__ __forceinline__ void cp_wait1() {
    asm volatile("cp.async.wait_group 1;");
}

__global__ __launch_bounds__(64) void scan_kernel(
    const float* __restrict__ lr, const float* __restrict__ state,
    float* __restrict__ wfinal)
{
    __shared__ float  ksm[2][2][RR][HD];   // [warp][stage][row][float] = 32KB
    __shared__ float4 gwbuf[2][2][64];     // [warp][buffer][16t x 4f4] = 4KB

    const int warp = (blockIdx.x * blockDim.x + threadIdx.x) >> 5;  // 0..511
    const int wl = (threadIdx.x >> 5);
    const int lane = threadIdx.x & 31;
    const int b = warp >> 7;
    const int i = warp & 127;
    const float eta = __ldg(lr);

    const float* kp = g_k + (size_t)b * SS * HD;
    const float* vp = g_v + (size_t)b * SS * HD + i;
    const float4* gp4 = (const float4*)(g_gram16 + (size_t)b * SS * 16);
    float* ep = g_e + (size_t)b * SS * HD + i;

    float4 Wr = *(const float4*)(state + (size_t)(b * HD + i) * HD + lane * 4);

    unsigned kbase = (unsigned)__cvta_generic_to_shared(&ksm[wl][0][0][lane * 4]);
    const unsigned KSTAGE = RR * HD * 4;   // 8192 bytes

    float vc[RR], vn1[RR], vn2[RR];
    // prologue: stage0 <- block0
#pragma unroll
    for (int r = 0; r < RR; r++)
        cp_async16(kbase + r * (HD * 4), kp + (size_t)r * HD + lane * 4);
    cp_commit();
#pragma unroll
    for (int r = 0; r < RR; r++) {
        vc[r]  = vp[(size_t)r * HD];
        vn1[r] = vp[(size_t)(RR + r) * HD];
    }
    gwbuf[wl][0][lane]      = gp4[lane];
    gwbuf[wl][0][lane + 32] = gp4[lane + 32];
    __syncwarp();

    for (int blk = 0; blk < NBLK; blk++) {
        const int T = blk * RR;
        const int cur = blk & 1;

        // chunk-start snapshot (Wr == W_{T-1}; CC/RR = 4)
        if ((blk & 3) == 0) {
            const int c = blk >> 2;
            *(float4*)(g_wsnap + ((size_t)((b * NCH + c) * HD + i)) * HD + lane * 4) = Wr;
        }

        // prefetch k for blk+1 into stage cur^1
        const int T1 = ((blk + 1 < NBLK) ? (blk + 1) : (NBLK - 1)) * RR;
#pragma unroll
        for (int r = 0; r < RR; r++)
            cp_async16(kbase + (cur ^ 1) * KSTAGE + r * (HD * 4),
                       kp + (size_t)(T1 + r) * HD + lane * 4);
        cp_commit();

        // v prefetch depth 2 (registers)
        const int T2 = ((blk + 2 < NBLK) ? (blk + 2) : (NBLK - 1)) * RR;
#pragma unroll
        for (int r = 0; r < RR; r++) vn2[r] = vp[(size_t)(T2 + r) * HD];

        // gram prefetch depth 1 (registers)
        float4 ga = gp4[(size_t)T1 * 4 + lane];
        float4 gb = gp4[(size_t)T1 * 4 + 32 + lane];

        // current k stage ready once only the just-issued group is outstanding
        cp_wait1();

        // 16 dots against fixed basis (each lane reads the 16B it copied)
        float d[RR];
#pragma unroll
        for (int r = 0; r < RR; r++) {
            float4 kk4 = *(const float4*)&ksm[wl][cur][r][lane * 4];
            d[r] = dot4(kk4, Wr);
        }
        // pipelined 5-stage shuffle reduction over 16 independent values
#pragma unroll
        for (int s = 16; s; s >>= 1) {
#pragma unroll
            for (int j = 0; j < RR; j++) d[j] += __shfl_xor_sync(~0u, d[j], s);
        }

        // publish next gram block
        gwbuf[wl][cur ^ 1][lane]      = ga;
        gwbuf[wl][cur ^ 1][lane + 32] = gb;
        __syncwarp();

        // serial scalar recurrence; Gram scalars read straight from smem
        const float* gbuf = (const float*)&gwbuf[wl][cur][0];
        float e[RR], ee[RR];
#pragma unroll
        for (int r = 0; r < RR; r++) {
            float acc = d[r] - vc[r];
#pragma unroll
            for (int dd2 = r; dd2 >= 1; --dd2)
                acc = fmaf(-ee[r - dd2], gbuf[r * 16 + dd2 - 1], acc);
            e[r] = acc;
            ee[r] = eta * acc;
        }

        if (lane == 0) {
#pragma unroll
            for (int r = 0; r < RR; r++) ep[(size_t)(T + r) * HD] = e[r];
        }

        // rank-16 update of basis (re-read k slices from smem)
#pragma unroll
        for (int r = 0; r < RR; r++) {
            float4 kk4 = *(const float4*)&ksm[wl][cur][r][lane * 4];
            Wr.x = fmaf(-ee[r], kk4.x, Wr.x);
            Wr.y = fmaf(-ee[r], kk4.y, Wr.y);
            Wr.z = fmaf(-ee[r], kk4.z, Wr.z);
            Wr.w = fmaf(-ee[r], kk4.w, Wr.w);
        }

        // rotate v buffers
#pragma unroll
        for (int r = 0; r < RR; r++) { vc[r] = vn1[r]; vn1[r] = vn2[r]; }
    }

    *(float4*)(wfinal + (size_t)(b * HD + i) * HD + lane * 4) = Wr;
}

// ---------------------------------------------------------------------------
// ypass: per (chunk c, batch b) CTA reconstructs
//   Y = Q_c * W0^T - eta * tril_strict(Q_c K_c^T) * E_c   (fp32 output)
// ---------------------------------------------------------------------------
__global__ __launch_bounds__(256) void ypass_kernel(const float* __restrict__ lr)
{
    const int c = blockIdx.x, b = blockIdx.y;
    const size_t base = ((size_t)b * SS + (size_t)c * CC) * HD;
    const float* Q  = g_q + base;
    const float* K  = g_k + base;
    const float* E  = g_e + base;
    const float* W0 = g_wsnap + (size_t)(b * NCH + c) * HD * HD;
    float* Y = g_y + base;
    const float eta = __ldg(lr);

    __shared__ float As2[CC][68];
    __shared__ float St[8][132];
    __shared__ float Qt[8][68];

    const int tid = threadIdx.x;
    const int ty = tid >> 4;
    const int tx = tid & 15;

    // ---- Phase A: A = Q K^T  (64x64, K=128) ----
    {
        float acc[4][4];
#pragma unroll
        for (int i = 0; i < 4; i++)
#pragma unroll
            for (int j = 0; j < 4; j++) acc[i][j] = 0.f;

        for (int h0 = 0; h0 < HD; h0 += 8) {
            __syncthreads();
            if (tid < 128) {
                const int t = tid >> 1, hh = (tid & 1) << 2;
                float4 qv = *(const float4*)(Q + (size_t)t * HD + h0 + hh);
                Qt[hh + 0][t] = qv.x; Qt[hh + 1][t] = qv.y;
                Qt[hh + 2][t] = qv.z; Qt[hh + 3][t] = qv.w;
            } else {
                const int m = tid - 128;
                const int s = m >> 1, hh = (m & 1) << 2;
                float4 kv = *(const float4*)(K + (size_t)s * HD + h0 + hh);
                St[hh + 0][s] = kv.x; St[hh + 1][s] = kv.y;
                St[hh + 2][s] = kv.z; St[hh + 3][s] = kv.w;
            }
            __syncthreads();
#pragma unroll
            for (int hh = 0; hh < 8; hh++) {
                float a[4], bb[4];
#pragma unroll
                for (int i = 0; i < 4; i++) a[i]  = Qt[hh][ty * 4 + i];
#pragma unroll
                for (int j = 0; j < 4; j++) bb[j] = St[hh][tx * 4 + j];
#pragma unroll
                for (int i = 0; i < 4; i++)
#pragma unroll
                    for (int j = 0; j < 4; j++) acc[i][j] = fmaf(a[i], bb[j], acc[i][j]);
            }
        }
        __syncthreads();
#pragma unroll
        for (int i = 0; i < 4; i++)
#pragma unroll
            for (int j = 0; j < 4; j++) {
                const int t = ty * 4 + i, s = tx * 4 + j;
                As2[t][s] = (s < t) ? (-eta * acc[i][j]) : 0.f;
            }
        __syncthreads();
    }

    // ---- Phase B: Y = Q W0^T + As2 * E  (64x128) ----
    float acc[4][8];
#pragma unroll
    for (int i = 0; i < 4; i++)
#pragma unroll
        for (int j = 0; j < 8; j++) acc[i][j] = 0.f;

    for (int h0 = 0; h0 < HD; h0 += 8) {
        __syncthreads();
        if (tid < 128) {
            const int t = tid >> 1, hh = (tid & 1) << 2;
            float4 qv = *(const float4*)(Q + (size_t)t * HD + h0 + hh);
            Qt[hh + 0][t] = qv.x; Qt[hh + 1][t] = qv.y;
            Qt[hh + 2][t] = qv.z; Qt[hh + 3][t] = qv.w;
        }
        {
            const int j = tid >> 1, hh = (tid & 1) << 2;
            float4 wv = *(const float4*)(W0 + (size_t)j * HD + h0 + hh);
            St[hh + 0][j] = wv.x; St[hh + 1][j] = wv.y;
            St[hh + 2][j] = wv.z; St[hh + 3][j] = wv.w;
        }
        __syncthreads();
#pragma unroll
        for (int hh = 0; hh < 8; hh++) {
            float a[4], bb[8];
#pragma unroll
            for (int i = 0; i < 4; i++) a[i]  = Qt[hh][ty * 4 + i];
#pragma unroll
            for (int j = 0; j < 8; j++) bb[j] = St[hh][tx * 8 + j];
#pragma unroll
            for (int i = 0; i < 4; i++)
#pragma unroll
                for (int j = 0; j < 8; j++) acc[i][j] = fmaf(a[i], bb[j], acc[i][j]);
        }
    }

    for (int s0 = 0; s0 < CC; s0 += 8) {
        __syncthreads();
        {
            const int ss = tid >> 5, j4 = (tid & 31) << 2;
            float4 ev = *(const float4*)(E + (size_t)(s0 + ss) * HD + j4);
            *(float4*)&St[ss][j4] = ev;
        }
        __syncthreads();
#pragma unroll
        for (int ss = 0; ss < 8; ss++) {
            float a[4], bb[8];
#pragma unroll
            for (int i = 0; i < 4; i++) a[i]  = As2[ty * 4 + i][s0 + ss];
#pragma unroll
            for (int j = 0; j < 8; j++) bb[j] = St[ss][tx * 8 + j];
#pragma unroll
            for (int i = 0; i < 4; i++)
#pragma unroll
                for (int j = 0; j < 8; j++) acc[i][j] = fmaf(a[i], bb[j], acc[i][j]);
        }
    }

#pragma unroll
    for (int i = 0; i < 4; i++) {
        float* yr = Y + (size_t)(ty * 4 + i) * HD + tx * 8;
        *(float4*)yr       = make_float4(acc[i][0], acc[i][1], acc[i][2], acc[i][3]);
        *(float4*)(yr + 4) = make_float4(acc[i][4], acc[i][5], acc[i][6], acc[i][7]);
    }
}

// ---------------------------------------------------------------------------
// kernel_launch — strictly serial, single stream (streams measured WORSE in
// this harness's graph replay; R13/R14 evidence). R12 order, splitx folded
// into qmma.
// ---------------------------------------------------------------------------
extern "C" void kernel_launch(void* const* d_in, const int* in_sizes, int n_in,
                              void* d_out, int out_size)
{
    const float* x  = (const float*)d_in[0];
    const float* Wq = (const float*)d_in[1];
    const float* Wk = (const float*)d_in[2];
    const float* Wv = (const float*)d_in[3];
    const float* Wo = (const float*)d_in[4];
    const float* lr = (const float*)d_in[5];
    const float* st = (const float*)d_in[6];
    float* out = (float*)d_out;

    // Wq transpose+split (x is converted inside qmma)
    splitwq_kernel<<<(DD * HD) / 256, 256>>>(Wq);

    // K,V projections in fp32 (fused)
    dim3 gkv(1, BS / 128, 2);
    kvgemm_kernel<<<gkv, 256>>>(x, Wk, Wv);

    // Q projection on tensor cores (3-term fp16 split, in-kernel x convert)
    qmma_kernel<<<BS / 128, 256>>>(x);

    // Gram scalars (k.k, distances 1..15)
    gram_kernel<<<(BB * SS) / 8, 256>>>();

    // Error scan (R12 version: one warp per row, 2 warps/CTA)
    scan_kernel<<<(BB * HD) / 2, 64>>>(lr, st, out + (size_t)BS * DD);

    // Parallel Y reconstruction per chunk (fp32 y)
    dim3 gy(NCH, BB);
    ypass_kernel<<<gy, 256>>>(lr);

    // Output projection in fp32 (y magnitude is unbounded; fp16 unsafe here)
    dim3 gout(DD / 128, BS / 128);
    outgemm_kernel<<<gout, 256>>>(Wo, out);
}

// round 17
// speedup vs baseline: 1.5723x; 1.0674x over previous
#include <cuda_runtime.h>
#include <cuda_fp16.h>
#include <math.h>

// Problem constants (fixed shapes from reference)
#define BB 4
#define SS 4096
#define DD 1024
#define HD 128
#define BS (BB*SS)   // 16384 rows
#define RR 16        // scan lookahead block size
#define NBLK (SS/RR) // 256
#define CC 64        // chunk size for y reconstruction
#define NCH (SS/CC)

// ---------------------------------------------------------------------------
// Scratch (device globals; no allocation allowed in kernel_launch)
// ---------------------------------------------------------------------------
__device__ float g_q[BB*SS*HD];
__device__ float g_k[BB*SS*HD];
__device__ float g_v[BB*SS*HD];
__device__ float g_e[BB*SS*HD];
__device__ float g_gram16[BB*SS*16];      // per (b,t): G1..G15, pad
__device__ float g_wsnap[BB*NCH*HD*HD];   // W at chunk starts

// fp16-split operands
__device__ __half g_wqh[HD*DD], g_wql[HD*DD];   // Wq^T [HD][DD]
__device__ __half g_woh[DD*HD], g_wol[DD*HD];   // Wo^T [DD][HD] (n-major)
__device__ __half g_yh[BS*HD], g_yl[BS*HD];     // per-row-scaled y split
__device__ float  g_yscale[BS];                 // power-of-2 row scales

__device__ __forceinline__ float dot4(float4 a, float4 b) {
    return fmaf(a.x, b.x, fmaf(a.y, b.y, fmaf(a.z, b.z, a.w * b.w)));
}

// ---------------------------------------------------------------------------
// splitw: transpose + split Wq and Wo into fp16 hi/lo
// ---------------------------------------------------------------------------
__global__ __launch_bounds__(256) void splitw_kernel(
    const float* __restrict__ Wq, const float* __restrict__ Wo)
{
    const int i = blockIdx.x * blockDim.x + threadIdx.x;
    const int m = i >> 17;              // 0: Wq, 1: Wo  (DD*HD = 2^17)
    const int r = i & 0x1FFFF;
    if (m == 0) {
        const int d = r >> 7, h = r & 127;     // Wq[d][h], d<DD, h<HD
        const float f = Wq[r];
        __half hi = __float2half_rn(f);
        __half lo = __float2half_rn(f - __half2float(hi));
        g_wqh[h * DD + d] = hi;
        g_wql[h * DD + d] = lo;
    } else {
        const int n = r >> 7, h = r & 127;     // WoT[n][h] = Wo[h][n]
        const float f = Wo[h * DD + n];
        __half hi = __float2half_rn(f);
        __half lo = __float2half_rn(f - __half2float(hi));
        g_woh[r] = hi;
        g_wol[r] = lo;
    }
}

// ---------------------------------------------------------------------------
// m16n8k16 wrapper
// ---------------------------------------------------------------------------
__device__ __forceinline__ void mma16816(float* c, const unsigned* a, const unsigned* b)
{
    asm volatile(
        "mma.sync.aligned.m16n8k16.row.col.f32.f16.f16.f32 "
        "{%0,%1,%2,%3},{%4,%5,%6,%7},{%8,%9},{%0,%1,%2,%3};"
        : "+f"(c[0]), "+f"(c[1]), "+f"(c[2]), "+f"(c[3])
        : "r"(a[0]), "r"(a[1]), "r"(a[2]), "r"(a[3]), "r"(b[0]), "r"(b[1]));
}

// convert 8 floats (two float4) -> int4 of hi half2s + int4 of lo half2s
__device__ __forceinline__ void cvt8_split(float4 a, float4 b, int4& hi, int4& lo)
{
    __half2 h[4], l[4];
    h[0] = __floats2half2_rn(a.x, a.y);
    h[1] = __floats2half2_rn(a.z, a.w);
    h[2] = __floats2half2_rn(b.x, b.y);
    h[3] = __floats2half2_rn(b.z, b.w);
    l[0] = __floats2half2_rn(a.x - __half2float(__low2half(h[0])),
                             a.y - __half2float(__high2half(h[0])));
    l[1] = __floats2half2_rn(a.z - __half2float(__low2half(h[1])),
                             a.w - __half2float(__high2half(h[1])));
    l[2] = __floats2half2_rn(b.x - __half2float(__low2half(h[2])),
                             b.y - __half2float(__high2half(h[2])));
    l[3] = __floats2half2_rn(b.z - __half2float(__low2half(h[3])),
                             b.w - __half2float(__high2half(h[3])));
    hi = *(int4*)&h[0];
    lo = *(int4*)&l[0];
}

// ---------------------------------------------------------------------------
// qmma: q = x * Wq^T (3-term fp16 split, x converted in-kernel)
// ---------------------------------------------------------------------------
__global__ __launch_bounds__(256) void qmma_kernel(const float* __restrict__ x)
{
    __shared__ unsigned AsH[128*20], AsL[128*20], BsH[128*20], BsL[128*20];

    const int bm = blockIdx.x;
    const int N = HD, K = DD;

    const int t = threadIdx.x;
    const int lane = t & 31, wid = t >> 5;
    const int g = lane >> 2, tg = lane & 3;
    const int warpM = wid >> 2, warpN = wid & 3;

    const int lr = t >> 1, lc = t & 1;
    const float* aPf = x + (size_t)(bm * 128 + lr) * K + lc * 16;
    const __half* bPh = g_wqh + (size_t)lr * K + lc * 16;
    const __half* bPl = g_wql + (size_t)lr * K + lc * 16;
    const int sts = lr * 20 + lc * 8;

    float c[4][4][4];
#pragma unroll
    for (int mt = 0; mt < 4; mt++)
#pragma unroll
        for (int nt = 0; nt < 4; nt++)
#pragma unroll
            for (int j = 0; j < 4; j++) c[mt][nt][j] = 0.f;

    float4 fa0 = *(const float4*)(aPf + 0);
    float4 fa1 = *(const float4*)(aPf + 4);
    float4 fa2 = *(const float4*)(aPf + 8);
    float4 fa3 = *(const float4*)(aPf + 12);
    int4 rb0  = *(const int4*)bPh;       int4 rb1  = *(const int4*)(bPh + 8);
    int4 rbl0 = *(const int4*)bPl;       int4 rbl1 = *(const int4*)(bPl + 8);
    {
        int4 h0, l0, h1, l1;
        cvt8_split(fa0, fa1, h0, l0);
        cvt8_split(fa2, fa3, h1, l1);
        *(int4*)&AsH[sts] = h0;   *(int4*)&AsH[sts + 4] = h1;
        *(int4*)&AsL[sts] = l0;   *(int4*)&AsL[sts + 4] = l1;
    }
    *(int4*)&BsH[sts] = rb0;   *(int4*)&BsH[sts + 4] = rb1;
    *(int4*)&BsL[sts] = rbl0;  *(int4*)&BsL[sts + 4] = rbl1;
    __syncthreads();

    const int KT = K / 32;
    for (int kt = 0; kt < KT; kt++) {
        if (kt + 1 < KT) {
            const int o = (kt + 1) * 32;
            fa0 = *(const float4*)(aPf + o);      fa1 = *(const float4*)(aPf + o + 4);
            fa2 = *(const float4*)(aPf + o + 8);  fa3 = *(const float4*)(aPf + o + 12);
            rb0  = *(const int4*)(bPh + o);       rb1  = *(const int4*)(bPh + o + 8);
            rbl0 = *(const int4*)(bPl + o);       rbl1 = *(const int4*)(bPl + o + 8);
        }
#pragma unroll
        for (int s = 0; s < 2; s++) {
            unsigned aH[4][4], aL[4][4], bH[4][2], bL[4][2];
#pragma unroll
            for (int mt = 0; mt < 4; mt++) {
                const int r0 = (warpM * 64 + mt * 16 + g) * 20 + s * 8 + tg;
                aH[mt][0] = AsH[r0];       aH[mt][1] = AsH[r0 + 160];
                aH[mt][2] = AsH[r0 + 4];   aH[mt][3] = AsH[r0 + 164];
                aL[mt][0] = AsL[r0];       aL[mt][1] = AsL[r0 + 160];
                aL[mt][2] = AsL[r0 + 4];   aL[mt][3] = AsL[r0 + 164];
            }
#pragma unroll
            for (int nt = 0; nt < 4; nt++) {
                const int n0 = (warpN * 32 + nt * 8 + g) * 20 + s * 8 + tg;
                bH[nt][0] = BsH[n0];  bH[nt][1] = BsH[n0 + 4];
                bL[nt][0] = BsL[n0];  bL[nt][1] = BsL[n0 + 4];
            }
#pragma unroll
            for (int mt = 0; mt < 4; mt++)
#pragma unroll
                for (int nt = 0; nt < 4; nt++) {
                    mma16816(c[mt][nt], aH[mt], bH[nt]);
                    mma16816(c[mt][nt], aH[mt], bL[nt]);
                    mma16816(c[mt][nt], aL[mt], bH[nt]);
                }
        }
        __syncthreads();
        if (kt + 1 < KT) {
            int4 h0, l0, h1, l1;
            cvt8_split(fa0, fa1, h0, l0);
            cvt8_split(fa2, fa3, h1, l1);
            *(int4*)&AsH[sts] = h0;   *(int4*)&AsH[sts + 4] = h1;
            *(int4*)&AsL[sts] = l0;   *(int4*)&AsL[sts + 4] = l1;
            *(int4*)&BsH[sts] = rb0;   *(int4*)&BsH[sts + 4] = rb1;
            *(int4*)&BsL[sts] = rbl0;  *(int4*)&BsL[sts + 4] = rbl1;
            __syncthreads();
        }
    }

#pragma unroll
    for (int mt = 0; mt < 4; mt++)
#pragma unroll
        for (int nt = 0; nt < 4; nt++) {
            const int row = bm * 128 + warpM * 64 + mt * 16 + g;
            const int col = warpN * 32 + nt * 8 + 2 * tg;
            *(float2*)&g_q[(size_t)row * N + col]       = make_float2(c[mt][nt][0], c[mt][nt][1]);
            *(float2*)&g_q[(size_t)(row + 8) * N + col] = make_float2(c[mt][nt][2], c[mt][nt][3]);
        }
}

// ---------------------------------------------------------------------------
// outmma: out = (scaled y) * Wo^T, 3-term fp16 split, per-row scale-back.
// M=BS, N=DD, K=HD=128. Grid (BS/128, DD/128) = (128, 8) -> 1024 CTAs.
// ---------------------------------------------------------------------------
__global__ __launch_bounds__(256) void outmma_kernel(float* __restrict__ out)
{
    __shared__ unsigned AsH[128*20], AsL[128*20], BsH[128*20], BsL[128*20];

    const int bm = blockIdx.x, bn = blockIdx.y;
    const int N = DD, K = HD;

    const int t = threadIdx.x;
    const int lane = t & 31, wid = t >> 5;
    const int g = lane >> 2, tg = lane & 3;
    const int warpM = wid >> 2, warpN = wid & 3;

    const int lr = t >> 1, lc = t & 1;
    const __half* aPh = g_yh + (size_t)(bm * 128 + lr) * K + lc * 16;
    const __half* aPl = g_yl + (size_t)(bm * 128 + lr) * K + lc * 16;
    const __half* bPh = g_woh + (size_t)(bn * 128 + lr) * K + lc * 16;
    const __half* bPl = g_wol + (size_t)(bn * 128 + lr) * K + lc * 16;
    const int sts = lr * 20 + lc * 8;

    float c[4][4][4];
#pragma unroll
    for (int mt = 0; mt < 4; mt++)
#pragma unroll
        for (int nt = 0; nt < 4; nt++)
#pragma unroll
            for (int j = 0; j < 4; j++) c[mt][nt][j] = 0.f;

    int4 ra0  = *(const int4*)aPh;       int4 ra1  = *(const int4*)(aPh + 8);
    int4 ral0 = *(const int4*)aPl;       int4 ral1 = *(const int4*)(aPl + 8);
    int4 rb0  = *(const int4*)bPh;       int4 rb1  = *(const int4*)(bPh + 8);
    int4 rbl0 = *(const int4*)bPl;       int4 rbl1 = *(const int4*)(bPl + 8);
    *(int4*)&AsH[sts] = ra0;   *(int4*)&AsH[sts + 4] = ra1;
    *(int4*)&AsL[sts] = ral0;  *(int4*)&AsL[sts + 4] = ral1;
    *(int4*)&BsH[sts] = rb0;   *(int4*)&BsH[sts + 4] = rb1;
    *(int4*)&BsL[sts] = rbl0;  *(int4*)&BsL[sts + 4] = rbl1;
    __syncthreads();

    const int KT = K / 32;   // 4
    for (int kt = 0; kt < KT; kt++) {
        if (kt + 1 < KT) {
            const int o = (kt + 1) * 32;
            ra0  = *(const int4*)(aPh + o);      ra1  = *(const int4*)(aPh + o + 8);
            ral0 = *(const int4*)(aPl + o);      ral1 = *(const int4*)(aPl + o + 8);
            rb0  = *(const int4*)(bPh + o);      rb1  = *(const int4*)(bPh + o + 8);
            rbl0 = *(const int4*)(bPl + o);      rbl1 = *(const int4*)(bPl + o + 8);
        }
#pragma unroll
        for (int s = 0; s < 2; s++) {
            unsigned aH[4][4], aL[4][4], bH[4][2], bL[4][2];
#pragma unroll
            for (int mt = 0; mt < 4; mt++) {
                const int r0 = (warpM * 64 + mt * 16 + g) * 20 + s * 8 + tg;
                aH[mt][0] = AsH[r0];       aH[mt][1] = AsH[r0 + 160];
                aH[mt][2] = AsH[r0 + 4];   aH[mt][3] = AsH[r0 + 164];
                aL[mt][0] = AsL[r0];       aL[mt][1] = AsL[r0 + 160];
                aL[mt][2] = AsL[r0 + 4];   aL[mt][3] = AsL[r0 + 164];
            }
#pragma unroll
            for (int nt = 0; nt < 4; nt++) {
                const int n0 = (warpN * 32 + nt * 8 + g) * 20 + s * 8 + tg;
                bH[nt][0] = BsH[n0];  bH[nt][1] = BsH[n0 + 4];
                bL[nt][0] = BsL[n0];  bL[nt][1] = BsL[n0 + 4];
            }
#pragma unroll
            for (int mt = 0; mt < 4; mt++)
#pragma unroll
                for (int nt = 0; nt < 4; nt++) {
                    mma16816(c[mt][nt], aH[mt], bH[nt]);
                    mma16816(c[mt][nt], aH[mt], bL[nt]);
                    mma16816(c[mt][nt], aL[mt], bH[nt]);
                }
        }
        __syncthreads();
        if (kt + 1 < KT) {
            *(int4*)&AsH[sts] = ra0;   *(int4*)&AsH[sts + 4] = ra1;
            *(int4*)&AsL[sts] = ral0;  *(int4*)&AsL[sts + 4] = ral1;
            *(int4*)&BsH[sts] = rb0;   *(int4*)&BsH[sts + 4] = rb1;
            *(int4*)&BsL[sts] = rbl0;  *(int4*)&BsL[sts + 4] = rbl1;
            __syncthreads();
        }
    }

#pragma unroll
    for (int mt = 0; mt < 4; mt++) {
        const int row0 = bm * 128 + warpM * 64 + mt * 16 + g;
        const float s0 = g_yscale[row0];
        const float s1 = g_yscale[row0 + 8];
#pragma unroll
        for (int nt = 0; nt < 4; nt++) {
            const int col = bn * 128 + warpN * 32 + nt * 8 + 2 * tg;
            *(float2*)&out[(size_t)row0 * N + col] =
                make_float2(c[mt][nt][0] * s0, c[mt][nt][1] * s0);
            *(float2*)&out[(size_t)(row0 + 8) * N + col] =
                make_float2(c[mt][nt][2] * s1, c[mt][nt][3] * s1);
        }
    }
}

// ---------------------------------------------------------------------------
// fp32 SGEMM body (known good) — used for K,V projections only
// ---------------------------------------------------------------------------
__device__ __forceinline__ void sgemm_body(
    const float* __restrict__ A, const float* __restrict__ Bm,
    float* __restrict__ C, int M, int N, int K, int bx, int by)
{
    __shared__ float As[8][128];
    __shared__ float Bs[8][132];

    const int tid = threadIdx.x;
    const int ty = tid >> 4;
    const int tx = tid & 15;
    const int a_r = tid >> 1;
    const int a_c = (tid & 1) << 2;
    const int b_r = tid >> 5;
    const int b_c = (tid & 31) << 2;

    const float* Ab = A + (size_t)by * 128 * K;
    const float* Bb = Bm + bx * 128;

    float acc[8][8];
#pragma unroll
    for (int i = 0; i < 8; i++)
#pragma unroll
        for (int j = 0; j < 8; j++) acc[i][j] = 0.f;

    for (int k0 = 0; k0 < K; k0 += 8) {
        float4 av = *(const float4*)(Ab + (size_t)a_r * K + k0 + a_c);
        float4 bv = *(const float4*)(Bb + (size_t)(k0 + b_r) * N + b_c);
        __syncthreads();
        As[a_c + 0][a_r] = av.x;
        As[a_c + 1][a_r] = av.y;
        As[a_c + 2][a_r] = av.z;
        As[a_c + 3][a_r] = av.w;
        *(float4*)&Bs[b_r][b_c] = bv;
        __syncthreads();
#pragma unroll
        for (int kk = 0; kk < 8; kk++) {
            float a[8], b[8];
#pragma unroll
            for (int i = 0; i < 8; i++) a[i] = As[kk][ty * 8 + i];
#pragma unroll
            for (int j = 0; j < 8; j++) b[j] = Bs[kk][tx * 8 + j];
#pragma unroll
            for (int i = 0; i < 8; i++)
#pragma unroll
                for (int j = 0; j < 8; j++) acc[i][j] = fmaf(a[i], b[j], acc[i][j]);
        }
    }

    float* Cb = C + (size_t)(by * 128 + ty * 8) * N + bx * 128 + tx * 8;
#pragma unroll
    for (int i = 0; i < 8; i++) {
        *(float4*)(Cb + (size_t)i * N)     = make_float4(acc[i][0], acc[i][1], acc[i][2], acc[i][3]);
        *(float4*)(Cb + (size_t)i * N + 4) = make_float4(acc[i][4], acc[i][5], acc[i][6], acc[i][7]);
    }
}

__global__ __launch_bounds__(256) void kvgemm_kernel(
    const float* __restrict__ x, const float* __restrict__ Wk,
    const float* __restrict__ Wv)
{
    const float* Bm = (blockIdx.z == 0) ? Wk : Wv;
    float* C = (blockIdx.z == 0) ? g_k : g_v;
    sgemm_body(x, Bm, C, BS, HD, DD, 0, blockIdx.y);
}

// ---------------------------------------------------------------------------
// Gram kernel: one warp per (b,t): G_d[t] = k_{t-d}.k_t for d=1..15
// ---------------------------------------------------------------------------
__global__ __launch_bounds__(256) void gram_kernel()
{
    const int w = (blockIdx.x * blockDim.x + threadIdx.x) >> 5;  // b*SS + t
    const int lane = threadIdx.x & 31;
    if (w >= BB * SS) return;
    const int t = w & (SS - 1);

    float4 kc = *(const float4*)(g_k + (size_t)w * HD + lane * 4);
    float dd[15];
#pragma unroll
    for (int d2 = 1; d2 <= 15; d2++) {
        float4 kd = make_float4(0.f, 0.f, 0.f, 0.f);
        if (t >= d2) kd = *(const float4*)(g_k + (size_t)(w - d2) * HD + lane * 4);
        dd[d2 - 1] = dot4(kd, kc);
    }
#pragma unroll
    for (int s = 16; s; s >>= 1) {
#pragma unroll
        for (int j = 0; j < 15; j++) dd[j] += __shfl_xor_sync(~0u, dd[j], s);
    }
    if (lane == 0) {
        float* gp = g_gram16 + (size_t)w * 16;
        *(float4*)(gp)      = make_float4(dd[0],  dd[1],  dd[2],  dd[3]);
        *(float4*)(gp + 4)  = make_float4(dd[4],  dd[5],  dd[6],  dd[7]);
        *(float4*)(gp + 8)  = make_float4(dd[8],  dd[9],  dd[10], dd[11]);
        *(float4*)(gp + 12) = make_float4(dd[12], dd[13], dd[14], 0.f);
    }
}

// ---------------------------------------------------------------------------
// Blocked-lookahead error scan, R=16 (R12 known-good version).
// ---------------------------------------------------------------------------
__device__ __forceinline__ void cp_async16(unsigned smem_addr, const void* gptr)
{
    asm volatile("cp.async.cg.shared.global [%0], [%1], 16;"
                 :: "r"(smem_addr), "l"(gptr));
}
__device__ __forceinline__ void cp_commit() {
    asm volatile("cp.async.commit_group;");
}
__device__ __forceinline__ void cp_wait1() {
    asm volatile("cp.async.wait_group 1;");
}

__global__ __launch_bounds__(64) void scan_kernel(
    const float* __restrict__ lr, const float* __restrict__ state,
    float* __restrict__ wfinal)
{
    __shared__ float  ksm[2][2][RR][HD];   // [warp][stage][row][float] = 32KB
    __shared__ float4 gwbuf[2][2][64];     // [warp][buffer][16t x 4f4] = 4KB

    const int warp = (blockIdx.x * blockDim.x + threadIdx.x) >> 5;  // 0..511
    const int wl = (threadIdx.x >> 5);
    const int lane = threadIdx.x & 31;
    const int b = warp >> 7;
    const int i = warp & 127;
    const float eta = __ldg(lr);

    const float* kp = g_k + (size_t)b * SS * HD;
    const float* vp = g_v + (size_t)b * SS * HD + i;
    const float4* gp4 = (const float4*)(g_gram16 + (size_t)b * SS * 16);
    float* ep = g_e + (size_t)b * SS * HD + i;

    float4 Wr = *(const float4*)(state + (size_t)(b * HD + i) * HD + lane * 4);

    unsigned kbase = (unsigned)__cvta_generic_to_shared(&ksm[wl][0][0][lane * 4]);
    const unsigned KSTAGE = RR * HD * 4;   // 8192 bytes

    float vc[RR], vn1[RR], vn2[RR];
#pragma unroll
    for (int r = 0; r < RR; r++)
        cp_async16(kbase + r * (HD * 4), kp + (size_t)r * HD + lane * 4);
    cp_commit();
#pragma unroll
    for (int r = 0; r < RR; r++) {
        vc[r]  = vp[(size_t)r * HD];
        vn1[r] = vp[(size_t)(RR + r) * HD];
    }
    gwbuf[wl][0][lane]      = gp4[lane];
    gwbuf[wl][0][lane + 32] = gp4[lane + 32];
    __syncwarp();

    for (int blk = 0; blk < NBLK; blk++) {
        const int T = blk * RR;
        const int cur = blk & 1;

        if ((blk & 3) == 0) {
            const int c = blk >> 2;
            *(float4*)(g_wsnap + ((size_t)((b * NCH + c) * HD + i)) * HD + lane * 4) = Wr;
        }

        const int T1 = ((blk + 1 < NBLK) ? (blk + 1) : (NBLK - 1)) * RR;
#pragma unroll
        for (int r = 0; r < RR; r++)
            cp_async16(kbase + (cur ^ 1) * KSTAGE + r * (HD * 4),
                       kp + (size_t)(T1 + r) * HD + lane * 4);
        cp_commit();

        const int T2 = ((blk + 2 < NBLK) ? (blk + 2) : (NBLK - 1)) * RR;
#pragma unroll
        for (int r = 0; r < RR; r++) vn2[r] = vp[(size_t)(T2 + r) * HD];

        float4 ga = gp4[(size_t)T1 * 4 + lane];
        float4 gb = gp4[(size_t)T1 * 4 + 32 + lane];

        cp_wait1();

        float d[RR];
#pragma unroll
        for (int r = 0; r < RR; r++) {
            float4 kk4 = *(const float4*)&ksm[wl][cur][r][lane * 4];
            d[r] = dot4(kk4, Wr);
        }
#pragma unroll
        for (int s = 16; s; s >>= 1) {
#pragma unroll
            for (int j = 0; j < RR; j++) d[j] += __shfl_xor_sync(~0u, d[j], s);
        }

        gwbuf[wl][cur ^ 1][lane]      = ga;
        gwbuf[wl][cur ^ 1][lane + 32] = gb;
        __syncwarp();

        const float* gbuf = (const float*)&gwbuf[wl][cur][0];
        float e[RR], ee[RR];
#pragma unroll
        for (int r = 0; r < RR; r++) {
            float acc = d[r] - vc[r];
#pragma unroll
            for (int dd2 = r; dd2 >= 1; --dd2)
                acc = fmaf(-ee[r - dd2], gbuf[r * 16 + dd2 - 1], acc);
            e[r] = acc;
            ee[r] = eta * acc;
        }

        if (lane == 0) {
#pragma unroll
            for (int r = 0; r < RR; r++) ep[(size_t)(T + r) * HD] = e[r];
        }

#pragma unroll
        for (int r = 0; r < RR; r++) {
            float4 kk4 = *(const float4*)&ksm[wl][cur][r][lane * 4];
            Wr.x = fmaf(-ee[r], kk4.x, Wr.x);
            Wr.y = fmaf(-ee[r], kk4.y, Wr.y);
            Wr.z = fmaf(-ee[r], kk4.z, Wr.z);
            Wr.w = fmaf(-ee[r], kk4.w, Wr.w);
        }

#pragma unroll
        for (int r = 0; r < RR; r++) { vc[r] = vn1[r]; vn1[r] = vn2[r]; }
    }

    *(float4*)(wfinal + (size_t)(b * HD + i) * HD + lane * 4) = Wr;
}

// ---------------------------------------------------------------------------
// ypass: per (chunk c, batch b) CTA:
//   Y = Q_c * W0^T - eta * tril_strict(Q_c K_c^T) * E_c
// Epilogue: per-row power-of-2 scale, fp16 hi/lo split to g_yh/g_yl + g_yscale.
// ---------------------------------------------------------------------------
__global__ __launch_bounds__(256) void ypass_kernel(const float* __restrict__ lr)
{
    const int c = blockIdx.x, b = blockIdx.y;
    const size_t base = ((size_t)b * SS + (size_t)c * CC) * HD;
    const int rowbase = b * SS + c * CC;
    const float* Q  = g_q + base;
    const float* K  = g_k + base;
    const float* E  = g_e + base;
    const float* W0 = g_wsnap + (size_t)(b * NCH + c) * HD * HD;
    const float eta = __ldg(lr);

    __shared__ float As2[CC][68];
    __shared__ float St[8][132];
    __shared__ float Qt[8][68];

    const int tid = threadIdx.x;
    const int ty = tid >> 4;
    const int tx = tid & 15;

    // ---- Phase A: A = Q K^T  (64x64, K=128) ----
    {
        float acc[4][4];
#pragma unroll
        for (int i = 0; i < 4; i++)
#pragma unroll
            for (int j = 0; j < 4; j++) acc[i][j] = 0.f;

        for (int h0 = 0; h0 < HD; h0 += 8) {
            __syncthreads();
            if (tid < 128) {
                const int t = tid >> 1, hh = (tid & 1) << 2;
                float4 qv = *(const float4*)(Q + (size_t)t * HD + h0 + hh);
                Qt[hh + 0][t] = qv.x; Qt[hh + 1][t] = qv.y;
                Qt[hh + 2][t] = qv.z; Qt[hh + 3][t] = qv.w;
            } else {
                const int m = tid - 128;
                const int s = m >> 1, hh = (m & 1) << 2;
                float4 kv = *(const float4*)(K + (size_t)s * HD + h0 + hh);
                St[hh + 0][s] = kv.x; St[hh + 1][s] = kv.y;
                St[hh + 2][s] = kv.z; St[hh + 3][s] = kv.w;
            }
            __syncthreads();
#pragma unroll
            for (int hh = 0; hh < 8; hh++) {
                float a[4], bb[4];
#pragma unroll
                for (int i = 0; i < 4; i++) a[i]  = Qt[hh][ty * 4 + i];
#pragma unroll
                for (int j = 0; j < 4; j++) bb[j] = St[hh][tx * 4 + j];
#pragma unroll
                for (int i = 0; i < 4; i++)
#pragma unroll
                    for (int j = 0; j < 4; j++) acc[i][j] = fmaf(a[i], bb[j], acc[i][j]);
            }
        }
        __syncthreads();
#pragma unroll
        for (int i = 0; i < 4; i++)
#pragma unroll
            for (int j = 0; j < 4; j++) {
                const int t = ty * 4 + i, s = tx * 4 + j;
                As2[t][s] = (s < t) ? (-eta * acc[i][j]) : 0.f;
            }
        __syncthreads();
    }

    // ---- Phase B: Y = Q W0^T + As2 * E  (64x128) ----
    float acc[4][8];
#pragma unroll
    for (int i = 0; i < 4; i++)
#pragma unroll
        for (int j = 0; j < 8; j++) acc[i][j] = 0.f;

    for (int h0 = 0; h0 < HD; h0 += 8) {
        __syncthreads();
        if (tid < 128) {
            const int t = tid >> 1, hh = (tid & 1) << 2;
            float4 qv = *(const float4*)(Q + (size_t)t * HD + h0 + hh);
            Qt[hh + 0][t] = qv.x; Qt[hh + 1][t] = qv.y;
            Qt[hh + 2][t] = qv.z; Qt[hh + 3][t] = qv.w;
        }
        {
            const int j = tid >> 1, hh = (tid & 1) << 2;
            float4 wv = *(const float4*)(W0 + (size_t)j * HD + h0 + hh);
            St[hh + 0][j] = wv.x; St[hh + 1][j] = wv.y;
            St[hh + 2][j] = wv.z; St[hh + 3][j] = wv.w;
        }
        __syncthreads();
#pragma unroll
        for (int hh = 0; hh < 8; hh++) {
            float a[4], bb[8];
#pragma unroll
            for (int i = 0; i < 4; i++) a[i]  = Qt[hh][ty * 4 + i];
#pragma unroll
            for (int j = 0; j < 8; j++) bb[j] = St[hh][tx * 8 + j];
#pragma unroll
            for (int i = 0; i < 4; i++)
#pragma unroll
                for (int j = 0; j < 8; j++) acc[i][j] = fmaf(a[i], bb[j], acc[i][j]);
        }
    }

    for (int s0 = 0; s0 < CC; s0 += 8) {
        __syncthreads();
        {
            const int ss = tid >> 5, j4 = (tid & 31) << 2;
            float4 ev = *(const float4*)(E + (size_t)(s0 + ss) * HD + j4);
            *(float4*)&St[ss][j4] = ev;
        }
        __syncthreads();
#pragma unroll
        for (int ss = 0; ss < 8; ss++) {
            float a[4], bb[8];
#pragma unroll
            for (int i = 0; i < 4; i++) a[i]  = As2[ty * 4 + i][s0 + ss];
#pragma unroll
            for (int j = 0; j < 8; j++) bb[j] = St[ss][tx * 8 + j];
#pragma unroll
            for (int i = 0; i < 4; i++)
#pragma unroll
                for (int j = 0; j < 8; j++) acc[i][j] = fmaf(a[i], bb[j], acc[i][j]);
        }
    }

    // ---- Epilogue: per-row scale (power of 2) + fp16 hi/lo split ----
    // The 16 threads owning row (ty*4+i) are lanes [base16, base16+16) of this
    // warp where base16 = (ty&1)*16; xor-shuffles with s<16 stay in-group.
#pragma unroll
    for (int i = 0; i < 4; i++) {
        float m = 0.f;
#pragma unroll
        for (int j = 0; j < 8; j++) m = fmaxf(m, fabsf(acc[i][j]));
#pragma unroll
        for (int s = 8; s; s >>= 1) m = fmaxf(m, __shfl_xor_sync(~0u, m, s));

        int ex = 0;
        if (m > 0.f) {
            ex = ilogbf(m) - 13;            // scaled max in [2^13, 2^14)
            if (ex < -20) ex = -20;
        }
        const float sc  = ldexpf(1.f, ex);
        const float inv = ldexpf(1.f, -ex);

        const int row = rowbase + ty * 4 + i;
        if (tx == 0) g_yscale[row] = sc;

        __half2 hv[4], lv[4];
#pragma unroll
        for (int j2 = 0; j2 < 4; j2++) {
            const float f0 = acc[i][2 * j2] * inv;
            const float f1 = acc[i][2 * j2 + 1] * inv;
            __half h0 = __float2half_rn(f0), h1 = __float2half_rn(f1);
            hv[j2] = __halves2half2(h0, h1);
            lv[j2] = __floats2half2_rn(f0 - __half2float(h0), f1 - __half2float(h1));
        }
        *(int4*)(g_yh + (size_t)row * HD + tx * 8) = *(int4*)&hv[0];
        *(int4*)(g_yl + (size_t)row * HD + tx * 8) = *(int4*)&lv[0];
    }
}

// ---------------------------------------------------------------------------
// kernel_launch — strictly serial, single stream.
// ---------------------------------------------------------------------------
extern "C" void kernel_launch(void* const* d_in, const int* in_sizes, int n_in,
                              void* d_out, int out_size)
{
    const float* x  = (const float*)d_in[0];
    const float* Wq = (const float*)d_in[1];
    const float* Wk = (const float*)d_in[2];
    const float* Wv = (const float*)d_in[3];
    const float* Wo = (const float*)d_in[4];
    const float* lr = (const float*)d_in[5];
    const float* st = (const float*)d_in[6];
    float* out = (float*)d_out;

    // Wq + Wo transpose+split
    splitw_kernel<<<(2 * DD * HD) / 256, 256>>>(Wq, Wo);

    // K,V projections in fp32 (fused)
    dim3 gkv(1, BS / 128, 2);
    kvgemm_kernel<<<gkv, 256>>>(x, Wk, Wv);

    // Q projection on tensor cores (3-term fp16 split, in-kernel x convert)
    qmma_kernel<<<BS / 128, 256>>>(x);

    // Gram scalars (k.k, distances 1..15)
    gram_kernel<<<(BB * SS) / 8, 256>>>();

    // Error scan
    scan_kernel<<<(BB * HD) / 2, 64>>>(lr, st, out + (size_t)BS * DD);

    // Y reconstruction; emits per-row-scaled fp16 split y
    dim3 gy(NCH, BB);
    ypass_kernel<<<gy, 256>>>(lr);

    // Output projection on tensor cores (scale-back in epilogue)
    dim3 gout(BS / 128, DD / 128);
    outmma_kernel<<<gout, 256>>>(out);
}